// round 15
// baseline (speedup 1.0000x reference)
#include <cuda_runtime.h>
#include <cuda_fp16.h>
#include <stdint.h>
#include <math.h>

#define BSZ 2
#define NP  2048
#define CH  256
#define FFNC 1024
#define NROW (BSZ*NP)
#define NBLK 256           // persistent IPOT grid (128 per batch, 16 rows each)

// ---------------- scratch (device globals; no allocations) ----------------
__device__ __half g_Qh[(size_t)BSZ*NP*NP];   // IPOT transport matrix (fp16), in place
__device__ __half g_Gh[(size_t)BSZ*NP*NP];   // exp(-cost/10) (fp16)
__device__ float g_Xtp[(size_t)BSZ*NP*CH];   // pts feat transposed [b,n,c]
__device__ float g_Xti[(size_t)BSZ*NP*CH];   // img feat transposed [b,n,c]
__device__ float g_imf[(size_t)BSZ*CH*NP];   // img projected feat [b,c,m] (pre-scaled by b)
__device__ float g_xcat[(size_t)BSZ*NP*2*CH];// [pf ; img_att] token-major [b,n,512]
__device__ float g_x[(size_t)BSZ*NP*CH];     // post out-proj (+LN in place)
__device__ float g_h[(size_t)BSZ*NP*FFNC];   // FFN hidden
__device__ float g_y2[(size_t)BSZ*NP*CH];    // FFN out + residual
__device__ float g_pcls[NROW], g_icls[NROW];
__device__ float g_bv[NROW], g_wv[NROW];
__device__ float g_v[3][NROW];               // triple-buffered column sums v = Q^T a

// per-batch grid-barrier state (zero-initialized; generations monotonic across replays)
__device__ unsigned g_cnt2[2][8];
__device__ unsigned g_cntm2[2];
__device__ volatile unsigned g_gen2[2];

// ---------------- per-batch software grid barrier (128 co-resident blocks) ----------------
__device__ __forceinline__ void gridbar(int batch, int lb) {
    __syncthreads();
    if (threadIdx.x == 0) {
        unsigned my = g_gen2[batch];
        __threadfence();
        unsigned s = lb & 7;                         // 8 groups of 16
        if (atomicAdd(&g_cnt2[batch][s], 1) == 15) {
            g_cnt2[batch][s] = 0;
            if (atomicAdd(&g_cntm2[batch], 1) == 7) {
                g_cntm2[batch] = 0;
                __threadfence();
                g_gen2[batch] = my + 1;
            }
        }
        while (g_gen2[batch] == my) { __nanosleep(32); }
        __threadfence();
    }
    __syncthreads();
}

// ---------------- transpose [b,C,N] -> [b,N,C], both tensors in one launch ----------------
__global__ void k_transpose2(const float* __restrict__ src0, const float* __restrict__ src1) {
    __shared__ float t[32][33];
    int z = blockIdx.z;                   // 0..3: (which, b)
    int which = z >> 1, b = z & 1;
    const float* srcp = which ? src1 : src0;
    float* dst = which ? g_Xti : g_Xtp;
    const float* s = srcp + (size_t)b * CH * NP;
    float* d = dst + (size_t)b * NP * CH;
    int n0 = blockIdx.x * 32, c0 = blockIdx.y * 32;
    for (int i = threadIdx.y; i < 32; i += 8)
        t[i][threadIdx.x] = s[(size_t)(c0 + i) * NP + n0 + threadIdx.x];
    __syncthreads();
    for (int i = threadIdx.y; i < 32; i += 8)
        d[(size_t)(n0 + i) * CH + c0 + threadIdx.x] = t[threadIdx.x][i];
}

// ---------------- pcls/icls = sigmoid(max over classes) ----------------
__global__ void k_cls(const float* __restrict__ pc, const float* __restrict__ ic) {
    int idx = blockIdx.x * 256 + threadIdx.x;   // 0..4095
    int b = idx >> 11, n = idx & (NP - 1);
    const float* p = pc + (size_t)b * 10 * NP + n;
    const float* q = ic + (size_t)b * 10 * NP + n;
    float mp = -1e30f, mi = -1e30f;
    #pragma unroll
    for (int c = 0; c < 10; c++) {
        mp = fmaxf(mp, p[(size_t)c * NP]);
        mi = fmaxf(mi, q[(size_t)c * NP]);
    }
    g_pcls[idx] = 1.f / (1.f + expf(-mp));
    g_icls[idx] = 1.f / (1.f + expf(-mi));
}

// ---------------- persistent IPOT (16 deposit slots, tail v-zeroing) ----------------
__global__ void __launch_bounds__(256, 2) k_ipot_persist(
    const float* __restrict__ ppos, const float* __restrict__ ipos) {
    extern __shared__ float sm[];         // 8KB fp32 b + 64KB fp16 slots = 72KB
    float* sh_b = sm;
    __half* sh_ph = (__half*)(sm + NP);   // 16 slots of NP halfs
    int tid = threadIdx.x, lane = tid & 31, wid = tid >> 5;
    int bid = blockIdx.x;
    int batch = bid >> 7, lb = bid & 127;
    int boff = batch * NP;
    int row0 = lb * 16;

    float pc0 = g_pcls[boff + row0 + wid];
    float pc1 = g_pcls[boff + row0 + wid + 8];
    float an_keep[2];
    an_keep[0] = 0.f; an_keep[1] = 0.f;

    float icz[8];
    {
        float4 i0 = *(const float4*)(g_icls + boff + tid * 8);
        float4 i1 = *(const float4*)(g_icls + boff + tid * 8 + 4);
        icz[0]=i0.x; icz[1]=i0.y; icz[2]=i0.z; icz[3]=i0.w;
        icz[4]=i1.x; icz[5]=i1.y; icz[6]=i1.z; icz[7]=i1.w;
    }

    // prologue: zero v[1] and v[2]
    {
        float4 z = make_float4(0.f, 0.f, 0.f, 0.f);
        float* v1 = g_v[1] + boff + tid * 8;
        float* v2 = g_v[2] + boff + tid * 8;
        *(float4*)v1 = z; *(float4*)(v1 + 4) = z;
        *(float4*)v2 = z; *(float4*)(v2 + 4) = z;
    }
    gridbar(batch, lb);

    for (int t = 1; t <= 100; t++) {
        // b into smem (t>1), vectorized
        if (t > 1) {
            const float4* vr = (const float4*)(g_v[(t - 1) % 3] + boff + tid * 8);
            float4 v0 = __ldcg(vr), v1 = __ldcg(vr + 1);
            float4 b0, b1;
            b0.x = __fdividef(icz[0], v0.x + 1e-6f);
            b0.y = __fdividef(icz[1], v0.y + 1e-6f);
            b0.z = __fdividef(icz[2], v0.z + 1e-6f);
            b0.w = __fdividef(icz[3], v0.w + 1e-6f);
            b1.x = __fdividef(icz[4], v1.x + 1e-6f);
            b1.y = __fdividef(icz[5], v1.y + 1e-6f);
            b1.z = __fdividef(icz[6], v1.z + 1e-6f);
            b1.w = __fdividef(icz[7], v1.w + 1e-6f);
            *(float4*)(sh_b + tid * 8) = b0;
            *(float4*)(sh_b + tid * 8 + 4) = b1;
        }
        __syncthreads();

        #pragma unroll
        for (int rr = 0; rr < 2; rr++) {
            __half* pwh = sh_ph + (wid * 2 + rr) * NP;     // private slot per (warp,rr)
            int row = row0 + wid + rr * 8;
            size_t base = (size_t)(boff + row) * NP;
            float qv[8][8];
            float u = 0.f;

            if (t == 1) {
                float2 pp = ((const float2*)ppos)[boff + row];
                const float2* ip = (const float2*)ipos + boff;
                #pragma unroll
                for (int j = 0; j < 8; j++) {
                    int c = (j * 32 + lane) * 8;
                    float qn[8];
                    #pragma unroll
                    for (int h = 0; h < 8; h++) {
                        float2 q2 = ip[c + h];
                        float dx = pp.x - q2.x, dy = pp.y - q2.y;
                        qn[h] = expf(-0.1f * sqrtf(dx * dx + dy * dy));
                    }
                    uint4 go; __half2* goh = (__half2*)&go;
                    uint4 qo; __half2* qoh = (__half2*)&qo;
                    #pragma unroll
                    for (int h = 0; h < 4; h++) {
                        goh[h] = __floats2half2_rn(qn[2 * h], qn[2 * h + 1]);
                        float a0 = fmaxf(qn[2 * h], 1e-6f), a1 = fmaxf(qn[2 * h + 1], 1e-6f);
                        qoh[h] = __floats2half2_rn(a0, a1);
                        qv[j][2 * h] = a0; qv[j][2 * h + 1] = a1;
                        u += a0 + a1;
                    }
                    *(uint4*)(g_Gh + base + c) = go;
                    *(uint4*)(g_Qh + base + c) = qo;
                }
                u *= (1.0f / NP);
            } else {
                float ap = an_keep[rr];
                #pragma unroll
                for (int j = 0; j < 8; j++) {
                    int c = (j * 32 + lane) * 8;
                    uint4 gq = *(const uint4*)(g_Gh + base + c);
                    uint4 qq = *(const uint4*)(g_Qh + base + c);
                    const __half2* gh = (const __half2*)&gq;
                    const __half2* qh = (const __half2*)&qq;
                    float4 b0 = *(const float4*)(sh_b + c);
                    float4 b1 = *(const float4*)(sh_b + c + 4);
                    float bb[8] = {b0.x, b0.y, b0.z, b0.w, b1.x, b1.y, b1.z, b1.w};
                    uint4 qo; __half2* qoh = (__half2*)&qo;
                    #pragma unroll
                    for (int h = 0; h < 4; h++) {
                        float2 gf = __half22float2(gh[h]);
                        float2 qf = __half22float2(qh[h]);
                        float n0 = fmaxf(gf.x * (ap * qf.x * bb[2 * h]), 1e-6f);
                        float n1 = fmaxf(gf.y * (ap * qf.y * bb[2 * h + 1]), 1e-6f);
                        qoh[h] = __floats2half2_rn(n0, n1);
                        qv[j][2 * h] = n0; qv[j][2 * h + 1] = n1;
                        u += n0 * bb[2 * h] + n1 * bb[2 * h + 1];
                    }
                    *(uint4*)(g_Qh + base + c) = qo;
                }
            }
            #pragma unroll
            for (int o = 16; o; o >>= 1) u += __shfl_xor_sync(0xffffffffu, u, o);
            float an = __fdividef((rr == 0 ? pc0 : pc1), u + 1e-6f);
            an_keep[rr] = an;

            // deposit an*q into this (warp,rr) slot — pure stores, no RMW
            #pragma unroll
            for (int j = 0; j < 8; j++) {
                int c = (j * 32 + lane) * 8;
                uint4 st; __half2* sth = (__half2*)&st;
                #pragma unroll
                for (int h = 0; h < 4; h++)
                    sth[h] = __floats2half2_rn(an * qv[j][2 * h], an * qv[j][2 * h + 1]);
                *(uint4*)(pwh + c) = st;
            }
        }
        __syncthreads();

        // combine 16 slots (half2), flush once per block
        float* vw = g_v[t % 3] + boff;
        #pragma unroll
        for (int jj = 0; jj < 4; jj++) {
            int m = 2 * tid + 512 * jj;
            float s0 = 0.f, s1 = 0.f;
            #pragma unroll
            for (int w = 0; w < 16; w++) {
                __half2 hv = *(const __half2*)(sh_ph + w * NP + m);
                float2 f = __half22float2(hv);
                s0 += f.x; s1 += f.y;
            }
            atomicAdd(vw + m, s0);
            atomicAdd(vw + m + 1, s1);
        }
        // tail: zero the buffer iteration t+1 will accumulate into (safe: last read at t-1)
        {
            float4 z = make_float4(0.f, 0.f, 0.f, 0.f);
            float* vz = g_v[(t + 1) % 3] + boff + tid * 8;
            *(float4*)vz = z; *(float4*)(vz + 4) = z;
        }
        gridbar(batch, lb);
    }

    // epilogue: b_final -> smem (+ g_bv once per batch)
    {
        const float4* vf = (const float4*)(g_v[1] + boff + tid * 8);
        float4 v0 = __ldcg(vf), v1 = __ldcg(vf + 1);
        float4 b0, b1;
        b0.x = __fdividef(icz[0], v0.x + 1e-6f);
        b0.y = __fdividef(icz[1], v0.y + 1e-6f);
        b0.z = __fdividef(icz[2], v0.z + 1e-6f);
        b0.w = __fdividef(icz[3], v0.w + 1e-6f);
        b1.x = __fdividef(icz[4], v1.x + 1e-6f);
        b1.y = __fdividef(icz[5], v1.y + 1e-6f);
        b1.z = __fdividef(icz[6], v1.z + 1e-6f);
        b1.w = __fdividef(icz[7], v1.w + 1e-6f);
        *(float4*)(sh_b + tid * 8) = b0;
        *(float4*)(sh_b + tid * 8 + 4) = b1;
        if (lb == 0) {
            *(float4*)(g_bv + boff + tid * 8) = b0;
            *(float4*)(g_bv + boff + tid * 8 + 4) = b1;
        }
    }
    __syncthreads();

    // row-normalization scale
    #pragma unroll
    for (int rr = 0; rr < 2; rr++) {
        int row = row0 + wid + rr * 8;
        size_t base = (size_t)(boff + row) * NP;
        float srs = 0.f;
        #pragma unroll
        for (int j = 0; j < 8; j++) {
            int c = (j * 32 + lane) * 8;
            uint4 qq = *(const uint4*)(g_Qh + base + c);
            const __half2* qh = (const __half2*)&qq;
            float4 b0 = *(const float4*)(sh_b + c);
            float4 b1 = *(const float4*)(sh_b + c + 4);
            float bb[8] = {b0.x, b0.y, b0.z, b0.w, b1.x, b1.y, b1.z, b1.w};
            #pragma unroll
            for (int h = 0; h < 4; h++) {
                float2 qf = __half22float2(qh[h]);
                srs += qf.x * bb[2 * h] + qf.y * bb[2 * h + 1];
            }
        }
        #pragma unroll
        for (int o = 16; o; o >>= 1) srs += __shfl_xor_sync(0xffffffffu, srs, o);
        if (lane == 0) {
            float a = an_keep[rr];
            g_wv[boff + row] = a / fmaxf(a * srs, 1e-12f);
        }
    }
}

// ---------------- tiled GEMM 64x128x32, 4x8/thread, double-buffered prefetch ----------------
template<int MODE>
__global__ void __launch_bounds__(256) k_gemm(const float* __restrict__ e0,
                                              const float* __restrict__ p0,
                                              const float* __restrict__ p1,
                                              const float* __restrict__ p2,
                                              const float* __restrict__ p3) {
    constexpr int BM = 64, BN = 128, BK = 32;
    constexpr int K = (MODE == 0 || MODE == 1 || MODE == 4) ? 256 :
                      (MODE == 2 ? 2048 : (MODE == 3 ? 512 : 1024));
    int b = blockIdx.z;
    const float* A = nullptr; const float* Bm;
    if constexpr (MODE == 0)      { A = g_Xtp + (size_t)b * NP * CH;  Bm = e0; }
    else if constexpr (MODE == 1) { A = e0;                           Bm = g_Xti + (size_t)b * NP * CH; }
    else if constexpr (MODE == 2) { Bm = g_imf + (size_t)b * CH * NP; }
    else if constexpr (MODE == 3) { A = g_xcat + (size_t)b * NP * 2 * CH; Bm = e0; }
    else if constexpr (MODE == 4) { A = g_x + (size_t)b * NP * CH;    Bm = e0; }
    else                          { A = g_h + (size_t)b * NP * FFNC;  Bm = e0; }

    __shared__ float Asm[BK][BM + 4];
    __shared__ float Bsm[BK][BN + 4];
    int i0 = blockIdx.y * BM, j0 = blockIdx.x * BN;
    int tx = threadIdx.x & 15, ty = threadIdx.x >> 4;
    float acc[4][8];
    #pragma unroll
    for (int r = 0; r < 4; r++)
        #pragma unroll
        for (int c = 0; c < 8; c++) acc[r][c] = 0.f;

    int aI[2], aK[2], bI[4], bK[4];
    #pragma unroll
    for (int s = 0; s < 2; s++) { int f4 = threadIdx.x + s * 256; aI[s] = f4 >> 3; aK[s] = (f4 & 7) * 4; }
    #pragma unroll
    for (int s = 0; s < 4; s++) { int f4 = threadIdx.x + s * 256; bI[s] = f4 >> 3; bK[s] = (f4 & 7) * 4; }
    int a2I = threadIdx.x >> 2, a2K = (threadIdx.x & 3) * 8;

    float4 pa[2]; uint4 pa2; float4 pb[4];

    if constexpr (MODE == 2) {
        const __half* Ah = g_Qh + (size_t)b * NP * NP;
        pa2 = *(const uint4*)(Ah + (size_t)(i0 + a2I) * K + a2K);
    } else {
        #pragma unroll
        for (int s = 0; s < 2; s++) pa[s] = *(const float4*)(A + (size_t)(i0 + aI[s]) * K + aK[s]);
    }
    #pragma unroll
    for (int s = 0; s < 4; s++) pb[s] = *(const float4*)(Bm + (size_t)(j0 + bI[s]) * K + bK[s]);

    for (int k0 = 0; k0 < K; k0 += BK) {
        if constexpr (MODE == 2) {
            const __half2* ah = (const __half2*)&pa2;
            #pragma unroll
            for (int h = 0; h < 4; h++) {
                float2 af = __half22float2(ah[h]);
                Asm[a2K + 2 * h][a2I] = af.x;
                Asm[a2K + 2 * h + 1][a2I] = af.y;
            }
        } else {
            #pragma unroll
            for (int s = 0; s < 2; s++) {
                Asm[aK[s] + 0][aI[s]] = pa[s].x; Asm[aK[s] + 1][aI[s]] = pa[s].y;
                Asm[aK[s] + 2][aI[s]] = pa[s].z; Asm[aK[s] + 3][aI[s]] = pa[s].w;
            }
        }
        #pragma unroll
        for (int s = 0; s < 4; s++) {
            Bsm[bK[s] + 0][bI[s]] = pb[s].x; Bsm[bK[s] + 1][bI[s]] = pb[s].y;
            Bsm[bK[s] + 2][bI[s]] = pb[s].z; Bsm[bK[s] + 3][bI[s]] = pb[s].w;
        }
        __syncthreads();

        int kn = k0 + BK;
        if (kn < K) {
            if constexpr (MODE == 2) {
                const __half* Ah = g_Qh + (size_t)b * NP * NP;
                pa2 = *(const uint4*)(Ah + (size_t)(i0 + a2I) * K + kn + a2K);
            } else {
                #pragma unroll
                for (int s = 0; s < 2; s++) pa[s] = *(const float4*)(A + (size_t)(i0 + aI[s]) * K + kn + aK[s]);
            }
            #pragma unroll
            for (int s = 0; s < 4; s++) pb[s] = *(const float4*)(Bm + (size_t)(j0 + bI[s]) * K + kn + bK[s]);
        }

        #pragma unroll
        for (int kk = 0; kk < BK; kk++) {
            float4 a0 = *(const float4*)&Asm[kk][ty * 4];
            float4 b0 = *(const float4*)&Bsm[kk][tx * 8];
            float4 b1 = *(const float4*)&Bsm[kk][tx * 8 + 4];
            float ar[4] = {a0.x, a0.y, a0.z, a0.w};
            float br[8] = {b0.x, b0.y, b0.z, b0.w, b1.x, b1.y, b1.z, b1.w};
            #pragma unroll
            for (int r = 0; r < 4; r++)
                #pragma unroll
                for (int c = 0; c < 8; c++) acc[r][c] += ar[r] * br[c];
        }
        __syncthreads();
    }

    int j = j0 + tx * 8;
    float bc[8], w0c[8], w1c[8], ppx[8], ppy[8], bvc[8];
    if constexpr (MODE == 0) {
        #pragma unroll
        for (int c = 0; c < 8; c++) {
            bc[c] = p0[j + c] + p1[j + c];
            w0c[c] = p2[2 * (j + c)];
            w1c[c] = p2[2 * (j + c) + 1];
        }
    } else if constexpr (MODE == 1) {
        #pragma unroll
        for (int c = 0; c < 8; c++) {
            float2 pp = ((const float2*)p3)[b * NP + j + c];
            ppx[c] = pp.x; ppy[c] = pp.y;
            bvc[c] = g_bv[b * NP + j + c];
        }
    } else if constexpr (MODE == 3 || MODE == 4 || MODE == 5) {
        #pragma unroll
        for (int c = 0; c < 8; c++) bc[c] = p0[j + c];
    }

    #pragma unroll
    for (int r = 0; r < 4; r++) {
        int i = i0 + ty * 4 + r;
        float vr[8];
        #pragma unroll
        for (int c = 0; c < 8; c++) vr[c] = acc[r][c];
        if constexpr (MODE == 0) {
            float2 pp = ((const float2*)p3)[b * NP + i];
            #pragma unroll
            for (int c = 0; c < 8; c++) vr[c] += bc[c] + w0c[c] * pp.x + w1c[c] * pp.y;
            float* o = g_xcat + ((size_t)(b * NP + i)) * (2 * CH) + j;
            *(float4*)o = make_float4(vr[0], vr[1], vr[2], vr[3]);
            *(float4*)(o + 4) = make_float4(vr[4], vr[5], vr[6], vr[7]);
        } else if constexpr (MODE == 1) {
            float bia = p0[i] + p1[i];
            float w0 = p2[2 * i], w1 = p2[2 * i + 1];
            #pragma unroll
            for (int c = 0; c < 8; c++) vr[c] = (vr[c] + bia + w0 * ppx[c] + w1 * ppy[c]) * bvc[c];
            float* o = g_imf + (size_t)b * CH * NP + (size_t)i * NP + j;
            *(float4*)o = make_float4(vr[0], vr[1], vr[2], vr[3]);
            *(float4*)(o + 4) = make_float4(vr[4], vr[5], vr[6], vr[7]);
        } else if constexpr (MODE == 2) {
            float w = g_wv[b * NP + i];
            #pragma unroll
            for (int c = 0; c < 8; c++) vr[c] *= w;
            float* o = g_xcat + ((size_t)(b * NP + i)) * (2 * CH) + CH + j;
            *(float4*)o = make_float4(vr[0], vr[1], vr[2], vr[3]);
            *(float4*)(o + 4) = make_float4(vr[4], vr[5], vr[6], vr[7]);
        } else if constexpr (MODE == 3) {
            #pragma unroll
            for (int c = 0; c < 8; c++) vr[c] += bc[c];
            float* o = g_x + ((size_t)(b * NP + i)) * CH + j;
            *(float4*)o = make_float4(vr[0], vr[1], vr[2], vr[3]);
            *(float4*)(o + 4) = make_float4(vr[4], vr[5], vr[6], vr[7]);
        } else if constexpr (MODE == 4) {
            #pragma unroll
            for (int c = 0; c < 8; c++) vr[c] = fmaxf(vr[c] + bc[c], 0.f);
            float* o = g_h + ((size_t)(b * NP + i)) * FFNC + j;
            *(float4*)o = make_float4(vr[0], vr[1], vr[2], vr[3]);
            *(float4*)(o + 4) = make_float4(vr[4], vr[5], vr[6], vr[7]);
        } else {
            const float* rsd = g_x + ((size_t)(b * NP + i)) * CH + j;
            float4 r0 = *(const float4*)rsd, r1 = *(const float4*)(rsd + 4);
            vr[0] += bc[0] + r0.x; vr[1] += bc[1] + r0.y; vr[2] += bc[2] + r0.z; vr[3] += bc[3] + r0.w;
            vr[4] += bc[4] + r1.x; vr[5] += bc[5] + r1.y; vr[6] += bc[6] + r1.z; vr[7] += bc[7] + r1.w;
            float* o = g_y2 + ((size_t)(b * NP + i)) * CH + j;
            *(float4*)o = make_float4(vr[0], vr[1], vr[2], vr[3]);
            *(float4*)(o + 4) = make_float4(vr[4], vr[5], vr[6], vr[7]);
        }
    }
}

// ---------------- LayerNorm in place on g_x ----------------
__global__ void k_ln(const float* __restrict__ gamma, const float* __restrict__ beta) {
    int row = blockIdx.x * 8 + (threadIdx.x >> 5);
    int lane = threadIdx.x & 31;
    float* x = g_x + (size_t)row * CH + lane * 8;
    float4 v0 = *(float4*)x;
    float4 v1 = *(float4*)(x + 4);
    float s = v0.x + v0.y + v0.z + v0.w + v1.x + v1.y + v1.z + v1.w;
    float s2 = v0.x * v0.x + v0.y * v0.y + v0.z * v0.z + v0.w * v0.w +
               v1.x * v1.x + v1.y * v1.y + v1.z * v1.z + v1.w * v1.w;
    #pragma unroll
    for (int o = 16; o; o >>= 1) {
        s  += __shfl_xor_sync(0xffffffffu, s, o);
        s2 += __shfl_xor_sync(0xffffffffu, s2, o);
    }
    float mu = s * (1.f / CH);
    float var = s2 * (1.f / CH) - mu * mu;
    float inv = rsqrtf(var + 1e-5f);
    int c = lane * 8;
    float4 g0 = *(const float4*)(gamma + c), g1 = *(const float4*)(gamma + c + 4);
    float4 b0 = *(const float4*)(beta + c),  b1 = *(const float4*)(beta + c + 4);
    v0.x = (v0.x - mu) * inv * g0.x + b0.x; v0.y = (v0.y - mu) * inv * g0.y + b0.y;
    v0.z = (v0.z - mu) * inv * g0.z + b0.z; v0.w = (v0.w - mu) * inv * g0.w + b0.w;
    v1.x = (v1.x - mu) * inv * g1.x + b1.x; v1.y = (v1.y - mu) * inv * g1.y + b1.y;
    v1.z = (v1.z - mu) * inv * g1.z + b1.z; v1.w = (v1.w - mu) * inv * g1.w + b1.w;
    *(float4*)x = v0;
    *(float4*)(x + 4) = v1;
}

// ---------------- final LN + prediction head + coalesced outputs ----------------
__global__ void k_final(const float* __restrict__ gamma, const float* __restrict__ beta,
                        const float* __restrict__ Wpred, const float* __restrict__ bpred,
                        const float* __restrict__ ppos,
                        float* __restrict__ out_x, float* __restrict__ out_np,
                        float* __restrict__ out_c) {
    __shared__ float tile[8][260];
    int tid = threadIdx.x;
    int row = blockIdx.x * 8 + (tid >> 5);
    int lane = tid & 31;
    int wid = tid >> 5;
    int b = row >> 11, n = row & (NP - 1);
    const float* y = g_y2 + (size_t)row * CH + lane * 8;
    float4 v0 = *(const float4*)y;
    float4 v1 = *(const float4*)(y + 4);
    float s = v0.x + v0.y + v0.z + v0.w + v1.x + v1.y + v1.z + v1.w;
    float s2 = v0.x * v0.x + v0.y * v0.y + v0.z * v0.z + v0.w * v0.w +
               v1.x * v1.x + v1.y * v1.y + v1.z * v1.z + v1.w * v1.w;
    #pragma unroll
    for (int o = 16; o; o >>= 1) {
        s  += __shfl_xor_sync(0xffffffffu, s, o);
        s2 += __shfl_xor_sync(0xffffffffu, s2, o);
    }
    float mu = s * (1.f / CH);
    float var = s2 * (1.f / CH) - mu * mu;
    float inv = rsqrtf(var + 1e-5f);
    int c = lane * 8;
    float4 g0 = *(const float4*)(gamma + c), g1 = *(const float4*)(gamma + c + 4);
    float4 b0 = *(const float4*)(beta + c),  b1 = *(const float4*)(beta + c + 4);
    v0.x = (v0.x - mu) * inv * g0.x + b0.x; v0.y = (v0.y - mu) * inv * g0.y + b0.y;
    v0.z = (v0.z - mu) * inv * g0.z + b0.z; v0.w = (v0.w - mu) * inv * g0.w + b0.w;
    v1.x = (v1.x - mu) * inv * g1.x + b1.x; v1.y = (v1.y - mu) * inv * g1.y + b1.y;
    v1.z = (v1.z - mu) * inv * g1.z + b1.z; v1.w = (v1.w - mu) * inv * g1.w + b1.w;

    float4 w00 = *(const float4*)(Wpred + c),      w01 = *(const float4*)(Wpred + c + 4);
    float4 w10 = *(const float4*)(Wpred + CH + c), w11 = *(const float4*)(Wpred + CH + c + 4);
    float d0 = v0.x * w00.x + v0.y * w00.y + v0.z * w00.z + v0.w * w00.w +
               v1.x * w01.x + v1.y * w01.y + v1.z * w01.z + v1.w * w01.w;
    float d1 = v0.x * w10.x + v0.y * w10.y + v0.z * w10.z + v0.w * w10.w +
               v1.x * w11.x + v1.y * w11.y + v1.z * w11.z + v1.w * w11.w;
    #pragma unroll
    for (int o = 16; o; o >>= 1) {
        d0 += __shfl_xor_sync(0xffffffffu, d0, o);
        d1 += __shfl_xor_sync(0xffffffffu, d1, o);
    }

    *(float4*)&tile[wid][c] = v0;
    *(float4*)&tile[wid][c + 4] = v1;

    if (lane == 0) {
        float2 pp = ((const float2*)ppos)[b * NP + n];
        float c0 = d0 + bpred[0] + pp.x;
        float c1 = d1 + bpred[1] + pp.y;
        out_c[(size_t)b * 2 * NP + n] = c0;
        out_c[(size_t)b * 2 * NP + NP + n] = c1;
        ((float2*)out_np)[b * NP + n] = make_float2(c0, c1);
    }
    __syncthreads();

    int col = tid;
    int n0 = (blockIdx.x * 8) & (NP - 1);
    int bb = (blockIdx.x * 8) >> 11;
    float* ox = out_x + (size_t)bb * CH * NP + (size_t)col * NP + n0;
    float4 o0 = make_float4(tile[0][col], tile[1][col], tile[2][col], tile[3][col]);
    float4 o1 = make_float4(tile[4][col], tile[5][col], tile[6][col], tile[7][col]);
    *(float4*)ox = o0;
    *(float4*)(ox + 4) = o1;
}

// ---------------- launch ----------------
extern "C" void kernel_launch(void* const* d_in, const int* in_sizes, int n_in,
                              void* d_out, int out_size) {
    const float* ptsf   = (const float*)d_in[0];
    const float* ppos   = (const float*)d_in[1];
    const float* imgf   = (const float*)d_in[2];
    const float* ipos   = (const float*)d_in[3];
    const float* ptscls = (const float*)d_in[4];
    const float* imgcls = (const float*)d_in[5];
    const float* Wp  = (const float*)d_in[6];  const float* bp  = (const float*)d_in[7];
    const float* Wi  = (const float*)d_in[8];  const float* bi  = (const float*)d_in[9];
    const float* Wqp = (const float*)d_in[10]; const float* bqp = (const float*)d_in[11];
    const float* Wkp = (const float*)d_in[12]; const float* bkp = (const float*)d_in[13];
    const float* Wout = (const float*)d_in[14]; const float* bout = (const float*)d_in[15];
    const float* gout = (const float*)d_in[16]; const float* betaout = (const float*)d_in[17];
    const float* Wf1 = (const float*)d_in[18]; const float* bf1 = (const float*)d_in[19];
    const float* Wf2 = (const float*)d_in[20]; const float* bf2 = (const float*)d_in[21];
    const float* gln = (const float*)d_in[22]; const float* bln = (const float*)d_in[23];
    const float* Wpred = (const float*)d_in[24]; const float* bpred = (const float*)d_in[25];

    float* out    = (float*)d_out;
    float* out_x  = out;                                   // [2,256,2048]
    float* out_np = out + (size_t)BSZ * CH * NP;           // [2,2048,2]
    float* out_c  = out_np + (size_t)BSZ * NP * 2;         // [2,2,2048]

    const int IPOT_SMEM = NP * (int)sizeof(float) + 16 * NP * (int)sizeof(__half);  // 72 KB
    cudaFuncSetAttribute(k_ipot_persist, cudaFuncAttributeMaxDynamicSharedMemorySize, IPOT_SMEM);

    dim3 tb(32, 8);
    k_cls<<<NROW / 256, 256>>>(ptscls, imgcls);                        // launch 1
    k_transpose2<<<dim3(NP / 32, CH / 32, 2 * BSZ), tb>>>(ptsf, imgf); // launch 2

    // launch 3: ALL 100 IPOT iterations
    k_ipot_persist<<<NBLK, 256, IPOT_SMEM>>>(ppos, ipos);

    // projections + positional embeddings
    k_gemm<0><<<dim3(CH / 128, NP / 64, BSZ), 256>>>(Wp, bp, bqp, Wqp, ppos);
    k_gemm<1><<<dim3(NP / 128, CH / 64, BSZ), 256>>>(Wi, bi, bkp, Wkp, ipos);  // *bv folded

    // attention GEMM: img_att = w ⊙ (Q_fp16 @ imf_scaled^T)
    k_gemm<2><<<dim3(CH / 128, NP / 64, BSZ), 256>>>(nullptr, nullptr, nullptr, nullptr, nullptr);
    // out projection + LN
    k_gemm<3><<<dim3(CH / 128, NP / 64, BSZ), 256>>>(Wout, bout, nullptr, nullptr, nullptr);
    k_ln<<<NROW / 8, 256>>>(gout, betaout);
    // FFN
    k_gemm<4><<<dim3(FFNC / 128, NP / 64, BSZ), 256>>>(Wf1, bf1, nullptr, nullptr, nullptr);
    k_gemm<5><<<dim3(CH / 128, NP / 64, BSZ), 256>>>(Wf2, bf2, nullptr, nullptr, nullptr);
    // final LN + head + outputs
    k_final<<<NROW / 8, 256>>>(gln, bln, Wpred, bpred, ppos, out_x, out_np, out_c);
}

// round 16
// speedup vs baseline: 1.0672x; 1.0672x over previous
#include <cuda_runtime.h>
#include <cuda_fp16.h>
#include <stdint.h>
#include <math.h>

#define BSZ 2
#define NP  2048
#define CH  256
#define FFNC 1024
#define NROW (BSZ*NP)
#define NBLK 256           // persistent IPOT grid (128 per batch, 16 rows each)

// ---------------- scratch (device globals; no allocations) ----------------
__device__ __half g_Qh[(size_t)BSZ*NP*NP];   // IPOT transport matrix (fp16), in place
__device__ __half g_Gh[(size_t)BSZ*NP*NP];   // exp(-cost/10) (fp16)
__device__ float g_Xtp[(size_t)BSZ*NP*CH];   // pts feat transposed [b,n,c]
__device__ float g_Xti[(size_t)BSZ*NP*CH];   // img feat transposed [b,n,c]
__device__ float g_imf[(size_t)BSZ*CH*NP];   // img projected feat [b,c,m] (pre-scaled by b)
__device__ float g_xcat[(size_t)BSZ*NP*2*CH];// [pf ; img_att] token-major [b,n,512]
__device__ float g_x[(size_t)BSZ*NP*CH];     // post out-proj (+LN in place)
__device__ float g_h[(size_t)BSZ*NP*FFNC];   // FFN hidden
__device__ float g_y2[(size_t)BSZ*NP*CH];    // FFN out + residual
__device__ float g_pcls[NROW], g_icls[NROW];
__device__ float g_bv[NROW], g_wv[NROW];
__device__ float g_v[3][NROW];               // triple-buffered column sums v = Q^T a

// per-batch grid-barrier state (zero-initialized; generations monotonic across replays)
__device__ unsigned g_cnt2[2][8];
__device__ unsigned g_cntm2[2];
__device__ volatile unsigned g_gen2[2];

// ---------------- per-batch software grid barrier (128 co-resident blocks) ----------------
__device__ __forceinline__ void gridbar(int batch, int lb) {
    __syncthreads();
    if (threadIdx.x == 0) {
        unsigned my = g_gen2[batch];
        __threadfence();
        unsigned s = lb & 7;                         // 8 groups of 16
        if (atomicAdd(&g_cnt2[batch][s], 1) == 15) {
            g_cnt2[batch][s] = 0;
            if (atomicAdd(&g_cntm2[batch], 1) == 7) {
                g_cntm2[batch] = 0;
                __threadfence();
                g_gen2[batch] = my + 1;
            }
        }
        while (g_gen2[batch] == my) { __nanosleep(32); }
        __threadfence();
    }
    __syncthreads();
}

// ---------------- transpose [b,C,N] -> [b,N,C], both tensors in one launch ----------------
__global__ void k_transpose2(const float* __restrict__ src0, const float* __restrict__ src1) {
    __shared__ float t[32][33];
    int z = blockIdx.z;                   // 0..3: (which, b)
    int which = z >> 1, b = z & 1;
    const float* srcp = which ? src1 : src0;
    float* dst = which ? g_Xti : g_Xtp;
    const float* s = srcp + (size_t)b * CH * NP;
    float* d = dst + (size_t)b * NP * CH;
    int n0 = blockIdx.x * 32, c0 = blockIdx.y * 32;
    for (int i = threadIdx.y; i < 32; i += 8)
        t[i][threadIdx.x] = s[(size_t)(c0 + i) * NP + n0 + threadIdx.x];
    __syncthreads();
    for (int i = threadIdx.y; i < 32; i += 8)
        d[(size_t)(n0 + i) * CH + c0 + threadIdx.x] = t[threadIdx.x][i];
}

// ---------------- pcls/icls = sigmoid(max over classes) ----------------
__global__ void k_cls(const float* __restrict__ pc, const float* __restrict__ ic) {
    int idx = blockIdx.x * 256 + threadIdx.x;   // 0..4095
    int b = idx >> 11, n = idx & (NP - 1);
    const float* p = pc + (size_t)b * 10 * NP + n;
    const float* q = ic + (size_t)b * 10 * NP + n;
    float mp = -1e30f, mi = -1e30f;
    #pragma unroll
    for (int c = 0; c < 10; c++) {
        mp = fmaxf(mp, p[(size_t)c * NP]);
        mi = fmaxf(mi, q[(size_t)c * NP]);
    }
    g_pcls[idx] = 1.f / (1.f + expf(-mp));
    g_icls[idx] = 1.f / (1.f + expf(-mi));
}

// ---------------- persistent IPOT (R13 structure: 8 slots + RMW) ----------------
__global__ void __launch_bounds__(256, 2) k_ipot_persist(
    const float* __restrict__ ppos, const float* __restrict__ ipos) {
    extern __shared__ float sm[];         // 8KB fp32 b + 32KB fp16 slots = 40KB
    float* sh_b = sm;
    __half* sh_ph = (__half*)(sm + NP);
    int tid = threadIdx.x, lane = tid & 31, wid = tid >> 5;
    int bid = blockIdx.x;
    int batch = bid >> 7, lb = bid & 127;
    int boff = batch * NP;
    int row0 = lb * 16;

    float pc0 = g_pcls[boff + row0 + wid];
    float pc1 = g_pcls[boff + row0 + wid + 8];
    float an_keep[2];
    an_keep[0] = 0.f; an_keep[1] = 0.f;

    float icz[8];
    {
        float4 i0 = *(const float4*)(g_icls + boff + tid * 8);
        float4 i1 = *(const float4*)(g_icls + boff + tid * 8 + 4);
        icz[0]=i0.x; icz[1]=i0.y; icz[2]=i0.z; icz[3]=i0.w;
        icz[4]=i1.x; icz[5]=i1.y; icz[6]=i1.z; icz[7]=i1.w;
    }

    {
        float4 z = make_float4(0.f, 0.f, 0.f, 0.f);
        float* vz = g_v[1] + boff + tid * 8;
        *(float4*)vz = z; *(float4*)(vz + 4) = z;
    }
    gridbar(batch, lb);

    for (int t = 1; t <= 100; t++) {
        {
            float4 z = make_float4(0.f, 0.f, 0.f, 0.f);
            float* vz = g_v[(t + 1) % 3] + boff + tid * 8;
            if (t > 1) {
                const float4* vr = (const float4*)(g_v[(t - 1) % 3] + boff + tid * 8);
                float4 v0 = __ldcg(vr), v1 = __ldcg(vr + 1);
                float4 b0, b1;
                b0.x = __fdividef(icz[0], v0.x + 1e-6f);
                b0.y = __fdividef(icz[1], v0.y + 1e-6f);
                b0.z = __fdividef(icz[2], v0.z + 1e-6f);
                b0.w = __fdividef(icz[3], v0.w + 1e-6f);
                b1.x = __fdividef(icz[4], v1.x + 1e-6f);
                b1.y = __fdividef(icz[5], v1.y + 1e-6f);
                b1.z = __fdividef(icz[6], v1.z + 1e-6f);
                b1.w = __fdividef(icz[7], v1.w + 1e-6f);
                *(float4*)(sh_b + tid * 8) = b0;
                *(float4*)(sh_b + tid * 8 + 4) = b1;
            }
            *(float4*)vz = z; *(float4*)(vz + 4) = z;
        }
        __syncthreads();

        __half* pwh = sh_ph + wid * NP;
        #pragma unroll
        for (int rr = 0; rr < 2; rr++) {
            int row = row0 + wid + rr * 8;
            size_t base = (size_t)(boff + row) * NP;
            float qv[8][8];
            float u = 0.f;

            if (t == 1) {
                float2 pp = ((const float2*)ppos)[boff + row];
                const float2* ip = (const float2*)ipos + boff;
                #pragma unroll
                for (int j = 0; j < 8; j++) {
                    int c = (j * 32 + lane) * 8;
                    float qn[8];
                    #pragma unroll
                    for (int h = 0; h < 8; h++) {
                        float2 q2 = ip[c + h];
                        float dx = pp.x - q2.x, dy = pp.y - q2.y;
                        qn[h] = expf(-0.1f * sqrtf(dx * dx + dy * dy));
                    }
                    uint4 go; __half2* goh = (__half2*)&go;
                    uint4 qo; __half2* qoh = (__half2*)&qo;
                    #pragma unroll
                    for (int h = 0; h < 4; h++) {
                        goh[h] = __floats2half2_rn(qn[2 * h], qn[2 * h + 1]);
                        float a0 = fmaxf(qn[2 * h], 1e-6f), a1 = fmaxf(qn[2 * h + 1], 1e-6f);
                        qoh[h] = __floats2half2_rn(a0, a1);
                        qv[j][2 * h] = a0; qv[j][2 * h + 1] = a1;
                        u += a0 + a1;
                    }
                    *(uint4*)(g_Gh + base + c) = go;
                    *(uint4*)(g_Qh + base + c) = qo;
                }
                u *= (1.0f / NP);
            } else {
                float ap = an_keep[rr];
                #pragma unroll
                for (int j = 0; j < 8; j++) {
                    int c = (j * 32 + lane) * 8;
                    uint4 gq = *(const uint4*)(g_Gh + base + c);
                    uint4 qq = *(const uint4*)(g_Qh + base + c);
                    const __half2* gh = (const __half2*)&gq;
                    const __half2* qh = (const __half2*)&qq;
                    float4 b0 = *(const float4*)(sh_b + c);
                    float4 b1 = *(const float4*)(sh_b + c + 4);
                    float bb[8] = {b0.x, b0.y, b0.z, b0.w, b1.x, b1.y, b1.z, b1.w};
                    uint4 qo; __half2* qoh = (__half2*)&qo;
                    #pragma unroll
                    for (int h = 0; h < 4; h++) {
                        float2 gf = __half22float2(gh[h]);
                        float2 qf = __half22float2(qh[h]);
                        float n0 = fmaxf(gf.x * (ap * qf.x * bb[2 * h]), 1e-6f);
                        float n1 = fmaxf(gf.y * (ap * qf.y * bb[2 * h + 1]), 1e-6f);
                        qoh[h] = __floats2half2_rn(n0, n1);
                        qv[j][2 * h] = n0; qv[j][2 * h + 1] = n1;
                        u += n0 * bb[2 * h] + n1 * bb[2 * h + 1];
                    }
                    *(uint4*)(g_Qh + base + c) = qo;
                }
            }
            #pragma unroll
            for (int o = 16; o; o >>= 1) u += __shfl_xor_sync(0xffffffffu, u, o);
            float an = __fdividef((rr == 0 ? pc0 : pc1), u + 1e-6f);
            an_keep[rr] = an;

            if (rr == 0) {
                #pragma unroll
                for (int j = 0; j < 8; j++) {
                    int c = (j * 32 + lane) * 8;
                    uint4 st; __half2* sth = (__half2*)&st;
                    #pragma unroll
                    for (int h = 0; h < 4; h++)
                        sth[h] = __floats2half2_rn(an * qv[j][2 * h], an * qv[j][2 * h + 1]);
                    *(uint4*)(pwh + c) = st;
                }
            } else {
                #pragma unroll
                for (int j = 0; j < 8; j++) {
                    int c = (j * 32 + lane) * 8;
                    uint4 old = *(uint4*)(pwh + c);
                    __half2* oh = (__half2*)&old;
                    uint4 st; __half2* sth = (__half2*)&st;
                    #pragma unroll
                    for (int h = 0; h < 4; h++) {
                        float2 f = __half22float2(oh[h]);
                        sth[h] = __floats2half2_rn(f.x + an * qv[j][2 * h],
                                                   f.y + an * qv[j][2 * h + 1]);
                    }
                    *(uint4*)(pwh + c) = st;
                }
            }
        }
        __syncthreads();

        float* vw = g_v[t % 3] + boff;
        #pragma unroll
        for (int jj = 0; jj < 4; jj++) {
            int m = 2 * tid + 512 * jj;
            float s0 = 0.f, s1 = 0.f;
            #pragma unroll
            for (int w = 0; w < 8; w++) {
                __half2 hv = *(const __half2*)(sh_ph + w * NP + m);
                float2 f = __half22float2(hv);
                s0 += f.x; s1 += f.y;
            }
            atomicAdd(vw + m, s0);
            atomicAdd(vw + m + 1, s1);
        }
        gridbar(batch, lb);
    }

    // epilogue: b_final -> smem (+ g_bv once per batch)
    {
        const float4* vf = (const float4*)(g_v[1] + boff + tid * 8);
        float4 v0 = __ldcg(vf), v1 = __ldcg(vf + 1);
        float4 b0, b1;
        b0.x = __fdividef(icz[0], v0.x + 1e-6f);
        b0.y = __fdividef(icz[1], v0.y + 1e-6f);
        b0.z = __fdividef(icz[2], v0.z + 1e-6f);
        b0.w = __fdividef(icz[3], v0.w + 1e-6f);
        b1.x = __fdividef(icz[4], v1.x + 1e-6f);
        b1.y = __fdividef(icz[5], v1.y + 1e-6f);
        b1.z = __fdividef(icz[6], v1.z + 1e-6f);
        b1.w = __fdividef(icz[7], v1.w + 1e-6f);
        *(float4*)(sh_b + tid * 8) = b0;
        *(float4*)(sh_b + tid * 8 + 4) = b1;
        if (lb == 0) {
            *(float4*)(g_bv + boff + tid * 8) = b0;
            *(float4*)(g_bv + boff + tid * 8 + 4) = b1;
        }
    }
    __syncthreads();

    // row-normalization scale
    #pragma unroll
    for (int rr = 0; rr < 2; rr++) {
        int row = row0 + wid + rr * 8;
        size_t base = (size_t)(boff + row) * NP;
        float srs = 0.f;
        #pragma unroll
        for (int j = 0; j < 8; j++) {
            int c = (j * 32 + lane) * 8;
            uint4 qq = *(const uint4*)(g_Qh + base + c);
            const __half2* qh = (const __half2*)&qq;
            float4 b0 = *(const float4*)(sh_b + c);
            float4 b1 = *(const float4*)(sh_b + c + 4);
            float bb[8] = {b0.x, b0.y, b0.z, b0.w, b1.x, b1.y, b1.z, b1.w};
            #pragma unroll
            for (int h = 0; h < 4; h++) {
                float2 qf = __half22float2(qh[h]);
                srs += qf.x * bb[2 * h] + qf.y * bb[2 * h + 1];
            }
        }
        #pragma unroll
        for (int o = 16; o; o >>= 1) srs += __shfl_xor_sync(0xffffffffu, srs, o);
        if (lane == 0) {
            float a = an_keep[rr];
            g_wv[boff + row] = a / fmaxf(a * srs, 1e-12f);
        }
    }
}

// ---------------- GEMM body (dynamic smem, explicit block coords) ----------------
template<int MODE>
__device__ __forceinline__ void gemm_body(int bx, int by, int b,
                                          const float* __restrict__ e0,
                                          const float* __restrict__ p0,
                                          const float* __restrict__ p1,
                                          const float* __restrict__ p2,
                                          const float* __restrict__ p3) {
    constexpr int BM = 64, BN = 128, BK = 32;
    constexpr int K = (MODE == 0 || MODE == 1 || MODE == 4) ? 256 :
                      (MODE == 2 ? 2048 : (MODE == 3 ? 512 : 1024));
    const float* A = nullptr; const float* Bm;
    if constexpr (MODE == 0)      { A = g_Xtp + (size_t)b * NP * CH;  Bm = e0; }
    else if constexpr (MODE == 1) { A = e0;                           Bm = g_Xti + (size_t)b * NP * CH; }
    else if constexpr (MODE == 2) { Bm = g_imf + (size_t)b * CH * NP; }
    else if constexpr (MODE == 3) { A = g_xcat + (size_t)b * NP * 2 * CH; Bm = e0; }
    else if constexpr (MODE == 4) { A = g_x + (size_t)b * NP * CH;    Bm = e0; }
    else                          { A = g_h + (size_t)b * NP * FFNC;  Bm = e0; }

    extern __shared__ float smg[];
    float (*Asm)[BM + 4] = (float(*)[BM + 4])smg;
    float (*Bsm)[BN + 4] = (float(*)[BN + 4])(smg + BK * (BM + 4));
    int i0 = by * BM, j0 = bx * BN;
    int tx = threadIdx.x & 15, ty = threadIdx.x >> 4;
    float acc[4][8];
    #pragma unroll
    for (int r = 0; r < 4; r++)
        #pragma unroll
        for (int c = 0; c < 8; c++) acc[r][c] = 0.f;

    int aI[2], aK[2], bI[4], bK[4];
    #pragma unroll
    for (int s = 0; s < 2; s++) { int f4 = threadIdx.x + s * 256; aI[s] = f4 >> 3; aK[s] = (f4 & 7) * 4; }
    #pragma unroll
    for (int s = 0; s < 4; s++) { int f4 = threadIdx.x + s * 256; bI[s] = f4 >> 3; bK[s] = (f4 & 7) * 4; }
    int a2I = threadIdx.x >> 2, a2K = (threadIdx.x & 3) * 8;

    float4 pa[2]; uint4 pa2; float4 pb[4];

    if constexpr (MODE == 2) {
        const __half* Ah = g_Qh + (size_t)b * NP * NP;
        pa2 = *(const uint4*)(Ah + (size_t)(i0 + a2I) * K + a2K);
    } else {
        #pragma unroll
        for (int s = 0; s < 2; s++) pa[s] = *(const float4*)(A + (size_t)(i0 + aI[s]) * K + aK[s]);
    }
    #pragma unroll
    for (int s = 0; s < 4; s++) pb[s] = *(const float4*)(Bm + (size_t)(j0 + bI[s]) * K + bK[s]);

    for (int k0 = 0; k0 < K; k0 += BK) {
        if constexpr (MODE == 2) {
            const __half2* ah = (const __half2*)&pa2;
            #pragma unroll
            for (int h = 0; h < 4; h++) {
                float2 af = __half22float2(ah[h]);
                Asm[a2K + 2 * h][a2I] = af.x;
                Asm[a2K + 2 * h + 1][a2I] = af.y;
            }
        } else {
            #pragma unroll
            for (int s = 0; s < 2; s++) {
                Asm[aK[s] + 0][aI[s]] = pa[s].x; Asm[aK[s] + 1][aI[s]] = pa[s].y;
                Asm[aK[s] + 2][aI[s]] = pa[s].z; Asm[aK[s] + 3][aI[s]] = pa[s].w;
            }
        }
        #pragma unroll
        for (int s = 0; s < 4; s++) {
            Bsm[bK[s] + 0][bI[s]] = pb[s].x; Bsm[bK[s] + 1][bI[s]] = pb[s].y;
            Bsm[bK[s] + 2][bI[s]] = pb[s].z; Bsm[bK[s] + 3][bI[s]] = pb[s].w;
        }
        __syncthreads();

        int kn = k0 + BK;
        if (kn < K) {
            if constexpr (MODE == 2) {
                const __half* Ah = g_Qh + (size_t)b * NP * NP;
                pa2 = *(const uint4*)(Ah + (size_t)(i0 + a2I) * K + kn + a2K);
            } else {
                #pragma unroll
                for (int s = 0; s < 2; s++) pa[s] = *(const float4*)(A + (size_t)(i0 + aI[s]) * K + kn + aK[s]);
            }
            #pragma unroll
            for (int s = 0; s < 4; s++) pb[s] = *(const float4*)(Bm + (size_t)(j0 + bI[s]) * K + kn + bK[s]);
        }

        #pragma unroll
        for (int kk = 0; kk < BK; kk++) {
            float4 a0 = *(const float4*)&Asm[kk][ty * 4];
            float4 b0 = *(const float4*)&Bsm[kk][tx * 8];
            float4 b1 = *(const float4*)&Bsm[kk][tx * 8 + 4];
            float ar[4] = {a0.x, a0.y, a0.z, a0.w};
            float br[8] = {b0.x, b0.y, b0.z, b0.w, b1.x, b1.y, b1.z, b1.w};
            #pragma unroll
            for (int r = 0; r < 4; r++)
                #pragma unroll
                for (int c = 0; c < 8; c++) acc[r][c] += ar[r] * br[c];
        }
        __syncthreads();
    }

    int j = j0 + tx * 8;
    float bc[8], w0c[8], w1c[8], ppx[8], ppy[8], bvc[8];
    if constexpr (MODE == 0) {
        #pragma unroll
        for (int c = 0; c < 8; c++) {
            bc[c] = p0[j + c] + p1[j + c];
            w0c[c] = p2[2 * (j + c)];
            w1c[c] = p2[2 * (j + c) + 1];
        }
    } else if constexpr (MODE == 1) {
        #pragma unroll
        for (int c = 0; c < 8; c++) {
            float2 pp = ((const float2*)p3)[b * NP + j + c];
            ppx[c] = pp.x; ppy[c] = pp.y;
            bvc[c] = g_bv[b * NP + j + c];
        }
    } else if constexpr (MODE == 3 || MODE == 4 || MODE == 5) {
        #pragma unroll
        for (int c = 0; c < 8; c++) bc[c] = p0[j + c];
    }

    #pragma unroll
    for (int r = 0; r < 4; r++) {
        int i = i0 + ty * 4 + r;
        float vr[8];
        #pragma unroll
        for (int c = 0; c < 8; c++) vr[c] = acc[r][c];
        if constexpr (MODE == 0) {
            float2 pp = ((const float2*)p3)[b * NP + i];
            #pragma unroll
            for (int c = 0; c < 8; c++) vr[c] += bc[c] + w0c[c] * pp.x + w1c[c] * pp.y;
            float* o = g_xcat + ((size_t)(b * NP + i)) * (2 * CH) + j;
            *(float4*)o = make_float4(vr[0], vr[1], vr[2], vr[3]);
            *(float4*)(o + 4) = make_float4(vr[4], vr[5], vr[6], vr[7]);
        } else if constexpr (MODE == 1) {
            float bia = p0[i] + p1[i];
            float w0 = p2[2 * i], w1 = p2[2 * i + 1];
            #pragma unroll
            for (int c = 0; c < 8; c++) vr[c] = (vr[c] + bia + w0 * ppx[c] + w1 * ppy[c]) * bvc[c];
            float* o = g_imf + (size_t)b * CH * NP + (size_t)i * NP + j;
            *(float4*)o = make_float4(vr[0], vr[1], vr[2], vr[3]);
            *(float4*)(o + 4) = make_float4(vr[4], vr[5], vr[6], vr[7]);
        } else if constexpr (MODE == 2) {
            float w = g_wv[b * NP + i];
            #pragma unroll
            for (int c = 0; c < 8; c++) vr[c] *= w;
            float* o = g_xcat + ((size_t)(b * NP + i)) * (2 * CH) + CH + j;
            *(float4*)o = make_float4(vr[0], vr[1], vr[2], vr[3]);
            *(float4*)(o + 4) = make_float4(vr[4], vr[5], vr[6], vr[7]);
        } else if constexpr (MODE == 3) {
            #pragma unroll
            for (int c = 0; c < 8; c++) vr[c] += bc[c];
            float* o = g_x + ((size_t)(b * NP + i)) * CH + j;
            *(float4*)o = make_float4(vr[0], vr[1], vr[2], vr[3]);
            *(float4*)(o + 4) = make_float4(vr[4], vr[5], vr[6], vr[7]);
        } else if constexpr (MODE == 4) {
            #pragma unroll
            for (int c = 0; c < 8; c++) vr[c] = fmaxf(vr[c] + bc[c], 0.f);
            float* o = g_h + ((size_t)(b * NP + i)) * FFNC + j;
            *(float4*)o = make_float4(vr[0], vr[1], vr[2], vr[3]);
            *(float4*)(o + 4) = make_float4(vr[4], vr[5], vr[6], vr[7]);
        } else {
            const float* rsd = g_x + ((size_t)(b * NP + i)) * CH + j;
            float4 r0 = *(const float4*)rsd, r1 = *(const float4*)(rsd + 4);
            vr[0] += bc[0] + r0.x; vr[1] += bc[1] + r0.y; vr[2] += bc[2] + r0.z; vr[3] += bc[3] + r0.w;
            vr[4] += bc[4] + r1.x; vr[5] += bc[5] + r1.y; vr[6] += bc[6] + r1.z; vr[7] += bc[7] + r1.w;
            float* o = g_y2 + ((size_t)(b * NP + i)) * CH + j;
            *(float4*)o = make_float4(vr[0], vr[1], vr[2], vr[3]);
            *(float4*)(o + 4) = make_float4(vr[4], vr[5], vr[6], vr[7]);
        }
    }
}

template<int MODE>
__global__ void __launch_bounds__(256) k_gemm(const float* __restrict__ e0,
                                              const float* __restrict__ p0,
                                              const float* __restrict__ p1,
                                              const float* __restrict__ p2,
                                              const float* __restrict__ p3) {
    gemm_body<MODE>(blockIdx.x, blockIdx.y, blockIdx.z, e0, p0, p1, p2, p3);
}

// fused gemm0+gemm1: 256 blocks, first 128 = mode0 (grid 2x32x2), rest = mode1 (16x4x2)
__global__ void __launch_bounds__(256) k_gemm01(
    const float* __restrict__ Wp, const float* __restrict__ bp,
    const float* __restrict__ bqp, const float* __restrict__ Wqp,
    const float* __restrict__ ppos,
    const float* __restrict__ Wi, const float* __restrict__ bi,
    const float* __restrict__ bkp, const float* __restrict__ Wkp,
    const float* __restrict__ ipos) {
    int id = blockIdx.x;
    if (id < 128) {
        int bz = id >> 6, r = id & 63;
        gemm_body<0>(r & 1, r >> 1, bz, Wp, bp, bqp, Wqp, ppos);
    } else {
        id -= 128;
        int bz = id >> 6, r = id & 63;
        gemm_body<1>(r & 15, r >> 4, bz, Wi, bi, bkp, Wkp, ipos);
    }
}

// ---------------- LayerNorm in place on g_x ----------------
__global__ void k_ln(const float* __restrict__ gamma, const float* __restrict__ beta) {
    int row = blockIdx.x * 8 + (threadIdx.x >> 5);
    int lane = threadIdx.x & 31;
    float* x = g_x + (size_t)row * CH + lane * 8;
    float4 v0 = *(float4*)x;
    float4 v1 = *(float4*)(x + 4);
    float s = v0.x + v0.y + v0.z + v0.w + v1.x + v1.y + v1.z + v1.w;
    float s2 = v0.x * v0.x + v0.y * v0.y + v0.z * v0.z + v0.w * v0.w +
               v1.x * v1.x + v1.y * v1.y + v1.z * v1.z + v1.w * v1.w;
    #pragma unroll
    for (int o = 16; o; o >>= 1) {
        s  += __shfl_xor_sync(0xffffffffu, s, o);
        s2 += __shfl_xor_sync(0xffffffffu, s2, o);
    }
    float mu = s * (1.f / CH);
    float var = s2 * (1.f / CH) - mu * mu;
    float inv = rsqrtf(var + 1e-5f);
    int c = lane * 8;
    float4 g0 = *(const float4*)(gamma + c), g1 = *(const float4*)(gamma + c + 4);
    float4 b0 = *(const float4*)(beta + c),  b1 = *(const float4*)(beta + c + 4);
    v0.x = (v0.x - mu) * inv * g0.x + b0.x; v0.y = (v0.y - mu) * inv * g0.y + b0.y;
    v0.z = (v0.z - mu) * inv * g0.z + b0.z; v0.w = (v0.w - mu) * inv * g0.w + b0.w;
    v1.x = (v1.x - mu) * inv * g1.x + b1.x; v1.y = (v1.y - mu) * inv * g1.y + b1.y;
    v1.z = (v1.z - mu) * inv * g1.z + b1.z; v1.w = (v1.w - mu) * inv * g1.w + b1.w;
    *(float4*)x = v0;
    *(float4*)(x + 4) = v1;
}

// ---------------- final LN + prediction head + coalesced outputs ----------------
__global__ void k_final(const float* __restrict__ gamma, const float* __restrict__ beta,
                        const float* __restrict__ Wpred, const float* __restrict__ bpred,
                        const float* __restrict__ ppos,
                        float* __restrict__ out_x, float* __restrict__ out_np,
                        float* __restrict__ out_c) {
    __shared__ float tile[8][260];
    int tid = threadIdx.x;
    int row = blockIdx.x * 8 + (tid >> 5);
    int lane = tid & 31;
    int wid = tid >> 5;
    int b = row >> 11, n = row & (NP - 1);
    const float* y = g_y2 + (size_t)row * CH + lane * 8;
    float4 v0 = *(const float4*)y;
    float4 v1 = *(const float4*)(y + 4);
    float s = v0.x + v0.y + v0.z + v0.w + v1.x + v1.y + v1.z + v1.w;
    float s2 = v0.x * v0.x + v0.y * v0.y + v0.z * v0.z + v0.w * v0.w +
               v1.x * v1.x + v1.y * v1.y + v1.z * v1.z + v1.w * v1.w;
    #pragma unroll
    for (int o = 16; o; o >>= 1) {
        s  += __shfl_xor_sync(0xffffffffu, s, o);
        s2 += __shfl_xor_sync(0xffffffffu, s2, o);
    }
    float mu = s * (1.f / CH);
    float var = s2 * (1.f / CH) - mu * mu;
    float inv = rsqrtf(var + 1e-5f);
    int c = lane * 8;
    float4 g0 = *(const float4*)(gamma + c), g1 = *(const float4*)(gamma + c + 4);
    float4 b0 = *(const float4*)(beta + c),  b1 = *(const float4*)(beta + c + 4);
    v0.x = (v0.x - mu) * inv * g0.x + b0.x; v0.y = (v0.y - mu) * inv * g0.y + b0.y;
    v0.z = (v0.z - mu) * inv * g0.z + b0.z; v0.w = (v0.w - mu) * inv * g0.w + b0.w;
    v1.x = (v1.x - mu) * inv * g1.x + b1.x; v1.y = (v1.y - mu) * inv * g1.y + b1.y;
    v1.z = (v1.z - mu) * inv * g1.z + b1.z; v1.w = (v1.w - mu) * inv * g1.w + b1.w;

    float4 w00 = *(const float4*)(Wpred + c),      w01 = *(const float4*)(Wpred + c + 4);
    float4 w10 = *(const float4*)(Wpred + CH + c), w11 = *(const float4*)(Wpred + CH + c + 4);
    float d0 = v0.x * w00.x + v0.y * w00.y + v0.z * w00.z + v0.w * w00.w +
               v1.x * w01.x + v1.y * w01.y + v1.z * w01.z + v1.w * w01.w;
    float d1 = v0.x * w10.x + v0.y * w10.y + v0.z * w10.z + v0.w * w10.w +
               v1.x * w11.x + v1.y * w11.y + v1.z * w11.z + v1.w * w11.w;
    #pragma unroll
    for (int o = 16; o; o >>= 1) {
        d0 += __shfl_xor_sync(0xffffffffu, d0, o);
        d1 += __shfl_xor_sync(0xffffffffu, d1, o);
    }

    *(float4*)&tile[wid][c] = v0;
    *(float4*)&tile[wid][c + 4] = v1;

    if (lane == 0) {
        float2 pp = ((const float2*)ppos)[b * NP + n];
        float c0 = d0 + bpred[0] + pp.x;
        float c1 = d1 + bpred[1] + pp.y;
        out_c[(size_t)b * 2 * NP + n] = c0;
        out_c[(size_t)b * 2 * NP + NP + n] = c1;
        ((float2*)out_np)[b * NP + n] = make_float2(c0, c1);
    }
    __syncthreads();

    int col = tid;
    int n0 = (blockIdx.x * 8) & (NP - 1);
    int bb = (blockIdx.x * 8) >> 11;
    float* ox = out_x + (size_t)bb * CH * NP + (size_t)col * NP + n0;
    float4 o0 = make_float4(tile[0][col], tile[1][col], tile[2][col], tile[3][col]);
    float4 o1 = make_float4(tile[4][col], tile[5][col], tile[6][col], tile[7][col]);
    *(float4*)ox = o0;
    *(float4*)(ox + 4) = o1;
}

// ---------------- launch ----------------
extern "C" void kernel_launch(void* const* d_in, const int* in_sizes, int n_in,
                              void* d_out, int out_size) {
    const float* ptsf   = (const float*)d_in[0];
    const float* ppos   = (const float*)d_in[1];
    const float* imgf   = (const float*)d_in[2];
    const float* ipos   = (const float*)d_in[3];
    const float* ptscls = (const float*)d_in[4];
    const float* imgcls = (const float*)d_in[5];
    const float* Wp  = (const float*)d_in[6];  const float* bp  = (const float*)d_in[7];
    const float* Wi  = (const float*)d_in[8];  const float* bi  = (const float*)d_in[9];
    const float* Wqp = (const float*)d_in[10]; const float* bqp = (const float*)d_in[11];
    const float* Wkp = (const float*)d_in[12]; const float* bkp = (const float*)d_in[13];
    const float* Wout = (const float*)d_in[14]; const float* bout = (const float*)d_in[15];
    const float* gout = (const float*)d_in[16]; const float* betaout = (const float*)d_in[17];
    const float* Wf1 = (const float*)d_in[18]; const float* bf1 = (const float*)d_in[19];
    const float* Wf2 = (const float*)d_in[20]; const float* bf2 = (const float*)d_in[21];
    const float* gln = (const float*)d_in[22]; const float* bln = (const float*)d_in[23];
    const float* Wpred = (const float*)d_in[24]; const float* bpred = (const float*)d_in[25];

    float* out    = (float*)d_out;
    float* out_x  = out;                                   // [2,256,2048]
    float* out_np = out + (size_t)BSZ * CH * NP;           // [2,2048,2]
    float* out_c  = out_np + (size_t)BSZ * NP * 2;         // [2,2,2048]

    const int IPOT_SMEM = NP * (int)sizeof(float) + 8 * NP * (int)sizeof(__half);  // 40 KB
    cudaFuncSetAttribute(k_ipot_persist, cudaFuncAttributeMaxDynamicSharedMemorySize, IPOT_SMEM);
    const int GEMM_SMEM = (32 * (64 + 4) + 32 * (128 + 4)) * (int)sizeof(float);   // 25600 B

    dim3 tb(32, 8);
    k_cls<<<NROW / 256, 256>>>(ptscls, imgcls);                        // launch 1
    k_transpose2<<<dim3(NP / 32, CH / 32, 2 * BSZ), tb>>>(ptsf, imgf); // launch 2

    // launch 3: ALL 100 IPOT iterations
    k_ipot_persist<<<NBLK, 256, IPOT_SMEM>>>(ppos, ipos);

    // fused projections + positional embeddings (mode0 + mode1 concurrently)
    k_gemm01<<<256, 256, GEMM_SMEM>>>(Wp, bp, bqp, Wqp, ppos, Wi, bi, bkp, Wkp, ipos);

    // attention GEMM: img_att = w ⊙ (Q_fp16 @ imf_scaled^T)
    k_gemm<2><<<dim3(CH / 128, NP / 64, BSZ), 256, GEMM_SMEM>>>(nullptr, nullptr, nullptr, nullptr, nullptr);
    // out projection + LN
    k_gemm<3><<<dim3(CH / 128, NP / 64, BSZ), 256, GEMM_SMEM>>>(Wout, bout, nullptr, nullptr, nullptr);
    k_ln<<<NROW / 8, 256>>>(gout, betaout);
    // FFN
    k_gemm<4><<<dim3(FFNC / 128, NP / 64, BSZ), 256, GEMM_SMEM>>>(Wf1, bf1, nullptr, nullptr, nullptr);
    k_gemm<5><<<dim3(CH / 128, NP / 64, BSZ), 256, GEMM_SMEM>>>(Wf2, bf2, nullptr, nullptr, nullptr);
    // final LN + head + outputs
    k_final<<<NROW / 8, 256>>>(gln, bln, Wpred, bpred, ppos, out_x, out_np, out_c);
}

// round 17
// speedup vs baseline: 1.0697x; 1.0024x over previous
#include <cuda_runtime.h>
#include <cuda_fp16.h>
#include <stdint.h>
#include <math.h>

#define BSZ 2
#define NP  2048
#define CH  256
#define FFNC 1024
#define NROW (BSZ*NP)
#define NBLK 256           // persistent IPOT grid (128 per batch, 16 rows each)

// ---------------- scratch (device globals; no allocations) ----------------
__device__ __half g_Qh[(size_t)BSZ*NP*NP];   // IPOT transport matrix (fp16), in place
__device__ __half g_Gh[(size_t)BSZ*NP*NP];   // exp(-cost/10) (fp16)
__device__ float g_Xtp[(size_t)BSZ*NP*CH];   // pts feat transposed [b,n,c]
__device__ float g_Xti[(size_t)BSZ*NP*CH];   // img feat transposed [b,n,c]
__device__ float g_imf[(size_t)BSZ*CH*NP];   // img projected feat [b,c,m] (pre-scaled by b)
__device__ float g_xcat[(size_t)BSZ*NP*2*CH];// [pf ; img_att] token-major [b,n,512]
__device__ float g_x[(size_t)BSZ*NP*CH];     // post out-proj (+LN in place)
__device__ float g_h[(size_t)BSZ*NP*FFNC];   // FFN hidden
__device__ float g_y2[(size_t)BSZ*NP*CH];    // FFN out + residual
__device__ float g_pcls[NROW], g_icls[NROW];
__device__ float g_bv[NROW], g_wv[NROW];
__device__ float g_v[3][NROW];               // triple-buffered column sums v = Q^T a

// per-batch grid-barrier state (zero-initialized; generations monotonic across replays)
__device__ unsigned g_cnt2[2][8];
__device__ unsigned g_cntm2[2];
__device__ volatile unsigned g_gen2[2];

// ---------------- per-batch software grid barrier (128 co-resident blocks) ----------------
__device__ __forceinline__ void gridbar(int batch, int lb) {
    __syncthreads();
    if (threadIdx.x == 0) {
        unsigned my = g_gen2[batch];
        __threadfence();
        unsigned s = lb & 7;                         // 8 groups of 16
        if (atomicAdd(&g_cnt2[batch][s], 1) == 15) {
            g_cnt2[batch][s] = 0;
            if (atomicAdd(&g_cntm2[batch], 1) == 7) {
                g_cntm2[batch] = 0;
                __threadfence();
                g_gen2[batch] = my + 1;
            }
        }
        while (g_gen2[batch] == my) { __nanosleep(32); }
        __threadfence();
    }
    __syncthreads();
}

// ---------------- transpose [b,C,N] -> [b,N,C], both tensors in one launch ----------------
__global__ void k_transpose2(const float* __restrict__ src0, const float* __restrict__ src1) {
    __shared__ float t[32][33];
    int z = blockIdx.z;                   // 0..3: (which, b)
    int which = z >> 1, b = z & 1;
    const float* srcp = which ? src1 : src0;
    float* dst = which ? g_Xti : g_Xtp;
    const float* s = srcp + (size_t)b * CH * NP;
    float* d = dst + (size_t)b * NP * CH;
    int n0 = blockIdx.x * 32, c0 = blockIdx.y * 32;
    for (int i = threadIdx.y; i < 32; i += 8)
        t[i][threadIdx.x] = s[(size_t)(c0 + i) * NP + n0 + threadIdx.x];
    __syncthreads();
    for (int i = threadIdx.y; i < 32; i += 8)
        d[(size_t)(n0 + i) * CH + c0 + threadIdx.x] = t[threadIdx.x][i];
}

// ---------------- pcls/icls = sigmoid(max over classes) ----------------
__global__ void k_cls(const float* __restrict__ pc, const float* __restrict__ ic) {
    int idx = blockIdx.x * 256 + threadIdx.x;   // 0..4095
    int b = idx >> 11, n = idx & (NP - 1);
    const float* p = pc + (size_t)b * 10 * NP + n;
    const float* q = ic + (size_t)b * 10 * NP + n;
    float mp = -1e30f, mi = -1e30f;
    #pragma unroll
    for (int c = 0; c < 10; c++) {
        mp = fmaxf(mp, p[(size_t)c * NP]);
        mi = fmaxf(mi, q[(size_t)c * NP]);
    }
    g_pcls[idx] = 1.f / (1.f + expf(-mp));
    g_icls[idx] = 1.f / (1.f + expf(-mi));
}

// ---------------- persistent IPOT (R13 structure: 8 slots + RMW) ----------------
__global__ void __launch_bounds__(256, 2) k_ipot_persist(
    const float* __restrict__ ppos, const float* __restrict__ ipos) {
    extern __shared__ float sm[];         // 8KB fp32 b + 32KB fp16 slots = 40KB
    float* sh_b = sm;
    __half* sh_ph = (__half*)(sm + NP);
    int tid = threadIdx.x, lane = tid & 31, wid = tid >> 5;
    int bid = blockIdx.x;
    int batch = bid >> 7, lb = bid & 127;
    int boff = batch * NP;
    int row0 = lb * 16;

    float pc0 = g_pcls[boff + row0 + wid];
    float pc1 = g_pcls[boff + row0 + wid + 8];
    float an_keep[2];
    an_keep[0] = 0.f; an_keep[1] = 0.f;

    float icz[8];
    {
        float4 i0 = *(const float4*)(g_icls + boff + tid * 8);
        float4 i1 = *(const float4*)(g_icls + boff + tid * 8 + 4);
        icz[0]=i0.x; icz[1]=i0.y; icz[2]=i0.z; icz[3]=i0.w;
        icz[4]=i1.x; icz[5]=i1.y; icz[6]=i1.z; icz[7]=i1.w;
    }

    {
        float4 z = make_float4(0.f, 0.f, 0.f, 0.f);
        float* vz = g_v[1] + boff + tid * 8;
        *(float4*)vz = z; *(float4*)(vz + 4) = z;
    }
    gridbar(batch, lb);

    for (int t = 1; t <= 100; t++) {
        {
            float4 z = make_float4(0.f, 0.f, 0.f, 0.f);
            float* vz = g_v[(t + 1) % 3] + boff + tid * 8;
            if (t > 1) {
                const float4* vr = (const float4*)(g_v[(t - 1) % 3] + boff + tid * 8);
                float4 v0 = __ldcg(vr), v1 = __ldcg(vr + 1);
                float4 b0, b1;
                b0.x = __fdividef(icz[0], v0.x + 1e-6f);
                b0.y = __fdividef(icz[1], v0.y + 1e-6f);
                b0.z = __fdividef(icz[2], v0.z + 1e-6f);
                b0.w = __fdividef(icz[3], v0.w + 1e-6f);
                b1.x = __fdividef(icz[4], v1.x + 1e-6f);
                b1.y = __fdividef(icz[5], v1.y + 1e-6f);
                b1.z = __fdividef(icz[6], v1.z + 1e-6f);
                b1.w = __fdividef(icz[7], v1.w + 1e-6f);
                *(float4*)(sh_b + tid * 8) = b0;
                *(float4*)(sh_b + tid * 8 + 4) = b1;
            }
            *(float4*)vz = z; *(float4*)(vz + 4) = z;
        }
        __syncthreads();

        __half* pwh = sh_ph + wid * NP;
        #pragma unroll
        for (int rr = 0; rr < 2; rr++) {
            int row = row0 + wid + rr * 8;
            size_t base = (size_t)(boff + row) * NP;
            float qv[8][8];
            float u = 0.f;

            if (t == 1) {
                float2 pp = ((const float2*)ppos)[boff + row];
                const float2* ip = (const float2*)ipos + boff;
                #pragma unroll
                for (int j = 0; j < 8; j++) {
                    int c = (j * 32 + lane) * 8;
                    float qn[8];
                    #pragma unroll
                    for (int h = 0; h < 8; h++) {
                        float2 q2 = ip[c + h];
                        float dx = pp.x - q2.x, dy = pp.y - q2.y;
                        qn[h] = expf(-0.1f * sqrtf(dx * dx + dy * dy));
                    }
                    uint4 go; __half2* goh = (__half2*)&go;
                    uint4 qo; __half2* qoh = (__half2*)&qo;
                    #pragma unroll
                    for (int h = 0; h < 4; h++) {
                        goh[h] = __floats2half2_rn(qn[2 * h], qn[2 * h + 1]);
                        float a0 = fmaxf(qn[2 * h], 1e-6f), a1 = fmaxf(qn[2 * h + 1], 1e-6f);
                        qoh[h] = __floats2half2_rn(a0, a1);
                        qv[j][2 * h] = a0; qv[j][2 * h + 1] = a1;
                        u += a0 + a1;
                    }
                    *(uint4*)(g_Gh + base + c) = go;
                    *(uint4*)(g_Qh + base + c) = qo;
                }
                u *= (1.0f / NP);
            } else {
                float ap = an_keep[rr];
                #pragma unroll
                for (int j = 0; j < 8; j++) {
                    int c = (j * 32 + lane) * 8;
                    uint4 gq = *(const uint4*)(g_Gh + base + c);
                    uint4 qq = *(const uint4*)(g_Qh + base + c);
                    const __half2* gh = (const __half2*)&gq;
                    const __half2* qh = (const __half2*)&qq;
                    float4 b0 = *(const float4*)(sh_b + c);
                    float4 b1 = *(const float4*)(sh_b + c + 4);
                    float bb[8] = {b0.x, b0.y, b0.z, b0.w, b1.x, b1.y, b1.z, b1.w};
                    uint4 qo; __half2* qoh = (__half2*)&qo;
                    #pragma unroll
                    for (int h = 0; h < 4; h++) {
                        float2 gf = __half22float2(gh[h]);
                        float2 qf = __half22float2(qh[h]);
                        float n0 = fmaxf(gf.x * (ap * qf.x * bb[2 * h]), 1e-6f);
                        float n1 = fmaxf(gf.y * (ap * qf.y * bb[2 * h + 1]), 1e-6f);
                        qoh[h] = __floats2half2_rn(n0, n1);
                        qv[j][2 * h] = n0; qv[j][2 * h + 1] = n1;
                        u += n0 * bb[2 * h] + n1 * bb[2 * h + 1];
                    }
                    *(uint4*)(g_Qh + base + c) = qo;
                }
            }
            #pragma unroll
            for (int o = 16; o; o >>= 1) u += __shfl_xor_sync(0xffffffffu, u, o);
            float an = __fdividef((rr == 0 ? pc0 : pc1), u + 1e-6f);
            an_keep[rr] = an;

            if (rr == 0) {
                #pragma unroll
                for (int j = 0; j < 8; j++) {
                    int c = (j * 32 + lane) * 8;
                    uint4 st; __half2* sth = (__half2*)&st;
                    #pragma unroll
                    for (int h = 0; h < 4; h++)
                        sth[h] = __floats2half2_rn(an * qv[j][2 * h], an * qv[j][2 * h + 1]);
                    *(uint4*)(pwh + c) = st;
                }
            } else {
                #pragma unroll
                for (int j = 0; j < 8; j++) {
                    int c = (j * 32 + lane) * 8;
                    uint4 old = *(uint4*)(pwh + c);
                    __half2* oh = (__half2*)&old;
                    uint4 st; __half2* sth = (__half2*)&st;
                    #pragma unroll
                    for (int h = 0; h < 4; h++) {
                        float2 f = __half22float2(oh[h]);
                        sth[h] = __floats2half2_rn(f.x + an * qv[j][2 * h],
                                                   f.y + an * qv[j][2 * h + 1]);
                    }
                    *(uint4*)(pwh + c) = st;
                }
            }
        }
        __syncthreads();

        float* vw = g_v[t % 3] + boff;
        #pragma unroll
        for (int jj = 0; jj < 4; jj++) {
            int m = 2 * tid + 512 * jj;
            float s0 = 0.f, s1 = 0.f;
            #pragma unroll
            for (int w = 0; w < 8; w++) {
                __half2 hv = *(const __half2*)(sh_ph + w * NP + m);
                float2 f = __half22float2(hv);
                s0 += f.x; s1 += f.y;
            }
            atomicAdd(vw + m, s0);
            atomicAdd(vw + m + 1, s1);
        }
        gridbar(batch, lb);
    }

    // epilogue: b_final -> smem (+ g_bv once per batch)
    {
        const float4* vf = (const float4*)(g_v[1] + boff + tid * 8);
        float4 v0 = __ldcg(vf), v1 = __ldcg(vf + 1);
        float4 b0, b1;
        b0.x = __fdividef(icz[0], v0.x + 1e-6f);
        b0.y = __fdividef(icz[1], v0.y + 1e-6f);
        b0.z = __fdividef(icz[2], v0.z + 1e-6f);
        b0.w = __fdividef(icz[3], v0.w + 1e-6f);
        b1.x = __fdividef(icz[4], v1.x + 1e-6f);
        b1.y = __fdividef(icz[5], v1.y + 1e-6f);
        b1.z = __fdividef(icz[6], v1.z + 1e-6f);
        b1.w = __fdividef(icz[7], v1.w + 1e-6f);
        *(float4*)(sh_b + tid * 8) = b0;
        *(float4*)(sh_b + tid * 8 + 4) = b1;
        if (lb == 0) {
            *(float4*)(g_bv + boff + tid * 8) = b0;
            *(float4*)(g_bv + boff + tid * 8 + 4) = b1;
        }
    }
    __syncthreads();

    // row-normalization scale
    #pragma unroll
    for (int rr = 0; rr < 2; rr++) {
        int row = row0 + wid + rr * 8;
        size_t base = (size_t)(boff + row) * NP;
        float srs = 0.f;
        #pragma unroll
        for (int j = 0; j < 8; j++) {
            int c = (j * 32 + lane) * 8;
            uint4 qq = *(const uint4*)(g_Qh + base + c);
            const __half2* qh = (const __half2*)&qq;
            float4 b0 = *(const float4*)(sh_b + c);
            float4 b1 = *(const float4*)(sh_b + c + 4);
            float bb[8] = {b0.x, b0.y, b0.z, b0.w, b1.x, b1.y, b1.z, b1.w};
            #pragma unroll
            for (int h = 0; h < 4; h++) {
                float2 qf = __half22float2(qh[h]);
                srs += qf.x * bb[2 * h] + qf.y * bb[2 * h + 1];
            }
        }
        #pragma unroll
        for (int o = 16; o; o >>= 1) srs += __shfl_xor_sync(0xffffffffu, srs, o);
        if (lane == 0) {
            float a = an_keep[rr];
            g_wv[boff + row] = a / fmaxf(a * srs, 1e-12f);
        }
    }
}

// ---------------- GEMM body: 128 threads, 64x128x32 tile, 8x8/thread ----------------
template<int MODE>
__device__ __forceinline__ void gemm_body(int bx, int by, int b,
                                          const float* __restrict__ e0,
                                          const float* __restrict__ p0,
                                          const float* __restrict__ p1,
                                          const float* __restrict__ p2,
                                          const float* __restrict__ p3) {
    constexpr int BM = 64, BN = 128, BK = 32;
    constexpr int K = (MODE == 0 || MODE == 1 || MODE == 4) ? 256 :
                      (MODE == 2 ? 2048 : (MODE == 3 ? 512 : 1024));
    const float* A = nullptr; const float* Bm;
    if constexpr (MODE == 0)      { A = g_Xtp + (size_t)b * NP * CH;  Bm = e0; }
    else if constexpr (MODE == 1) { A = e0;                           Bm = g_Xti + (size_t)b * NP * CH; }
    else if constexpr (MODE == 2) { Bm = g_imf + (size_t)b * CH * NP; }
    else if constexpr (MODE == 3) { A = g_xcat + (size_t)b * NP * 2 * CH; Bm = e0; }
    else if constexpr (MODE == 4) { A = g_x + (size_t)b * NP * CH;    Bm = e0; }
    else                          { A = g_h + (size_t)b * NP * FFNC;  Bm = e0; }

    extern __shared__ float smg[];
    float (*Asm)[BM + 4] = (float(*)[BM + 4])smg;
    float (*Bsm)[BN + 4] = (float(*)[BN + 4])(smg + BK * (BM + 4));
    int i0 = by * BM, j0 = bx * BN;
    int tx = threadIdx.x & 15, ty = threadIdx.x >> 4;    // tx 0..15, ty 0..7
    float acc[8][8];
    #pragma unroll
    for (int r = 0; r < 8; r++)
        #pragma unroll
        for (int c = 0; c < 8; c++) acc[r][c] = 0.f;

    int aI[4], aK[4], bI[8], bK[8];
    #pragma unroll
    for (int s = 0; s < 4; s++) { int f4 = threadIdx.x + s * 128; aI[s] = f4 >> 3; aK[s] = (f4 & 7) * 4; }
    #pragma unroll
    for (int s = 0; s < 8; s++) { int f4 = threadIdx.x + s * 128; bI[s] = f4 >> 3; bK[s] = (f4 & 7) * 4; }
    int a2I[2], a2K[2];
    #pragma unroll
    for (int s = 0; s < 2; s++) { int f = threadIdx.x + s * 128; a2I[s] = f >> 2; a2K[s] = (f & 3) * 8; }

    float4 pa[4]; uint4 pa2[2]; float4 pb[8];

    if constexpr (MODE == 2) {
        const __half* Ah = g_Qh + (size_t)b * NP * NP;
        #pragma unroll
        for (int s = 0; s < 2; s++)
            pa2[s] = *(const uint4*)(Ah + (size_t)(i0 + a2I[s]) * K + a2K[s]);
    } else {
        #pragma unroll
        for (int s = 0; s < 4; s++) pa[s] = *(const float4*)(A + (size_t)(i0 + aI[s]) * K + aK[s]);
    }
    #pragma unroll
    for (int s = 0; s < 8; s++) pb[s] = *(const float4*)(Bm + (size_t)(j0 + bI[s]) * K + bK[s]);

    for (int k0 = 0; k0 < K; k0 += BK) {
        if constexpr (MODE == 2) {
            #pragma unroll
            for (int s = 0; s < 2; s++) {
                const __half2* ah = (const __half2*)&pa2[s];
                #pragma unroll
                for (int h = 0; h < 4; h++) {
                    float2 af = __half22float2(ah[h]);
                    Asm[a2K[s] + 2 * h][a2I[s]] = af.x;
                    Asm[a2K[s] + 2 * h + 1][a2I[s]] = af.y;
                }
            }
        } else {
            #pragma unroll
            for (int s = 0; s < 4; s++) {
                Asm[aK[s] + 0][aI[s]] = pa[s].x; Asm[aK[s] + 1][aI[s]] = pa[s].y;
                Asm[aK[s] + 2][aI[s]] = pa[s].z; Asm[aK[s] + 3][aI[s]] = pa[s].w;
            }
        }
        #pragma unroll
        for (int s = 0; s < 8; s++) {
            Bsm[bK[s] + 0][bI[s]] = pb[s].x; Bsm[bK[s] + 1][bI[s]] = pb[s].y;
            Bsm[bK[s] + 2][bI[s]] = pb[s].z; Bsm[bK[s] + 3][bI[s]] = pb[s].w;
        }
        __syncthreads();

        int kn = k0 + BK;
        if (kn < K) {
            if constexpr (MODE == 2) {
                const __half* Ah = g_Qh + (size_t)b * NP * NP;
                #pragma unroll
                for (int s = 0; s < 2; s++)
                    pa2[s] = *(const uint4*)(Ah + (size_t)(i0 + a2I[s]) * K + kn + a2K[s]);
            } else {
                #pragma unroll
                for (int s = 0; s < 4; s++) pa[s] = *(const float4*)(A + (size_t)(i0 + aI[s]) * K + kn + aK[s]);
            }
            #pragma unroll
            for (int s = 0; s < 8; s++) pb[s] = *(const float4*)(Bm + (size_t)(j0 + bI[s]) * K + kn + bK[s]);
        }

        #pragma unroll
        for (int kk = 0; kk < BK; kk++) {
            float4 a0 = *(const float4*)&Asm[kk][ty * 8];
            float4 a1 = *(const float4*)&Asm[kk][ty * 8 + 4];
            float4 b0 = *(const float4*)&Bsm[kk][tx * 8];
            float4 b1 = *(const float4*)&Bsm[kk][tx * 8 + 4];
            float ar[8] = {a0.x, a0.y, a0.z, a0.w, a1.x, a1.y, a1.z, a1.w};
            float br[8] = {b0.x, b0.y, b0.z, b0.w, b1.x, b1.y, b1.z, b1.w};
            #pragma unroll
            for (int r = 0; r < 8; r++)
                #pragma unroll
                for (int c = 0; c < 8; c++) acc[r][c] += ar[r] * br[c];
        }
        __syncthreads();
    }

    int j = j0 + tx * 8;
    float bc[8], w0c[8], w1c[8], ppx[8], ppy[8], bvc[8];
    if constexpr (MODE == 0) {
        #pragma unroll
        for (int c = 0; c < 8; c++) {
            bc[c] = p0[j + c] + p1[j + c];
            w0c[c] = p2[2 * (j + c)];
            w1c[c] = p2[2 * (j + c) + 1];
        }
    } else if constexpr (MODE == 1) {
        #pragma unroll
        for (int c = 0; c < 8; c++) {
            float2 pp = ((const float2*)p3)[b * NP + j + c];
            ppx[c] = pp.x; ppy[c] = pp.y;
            bvc[c] = g_bv[b * NP + j + c];
        }
    } else if constexpr (MODE == 3 || MODE == 4 || MODE == 5) {
        #pragma unroll
        for (int c = 0; c < 8; c++) bc[c] = p0[j + c];
    }

    #pragma unroll
    for (int r = 0; r < 8; r++) {
        int i = i0 + ty * 8 + r;
        float vr[8];
        #pragma unroll
        for (int c = 0; c < 8; c++) vr[c] = acc[r][c];
        if constexpr (MODE == 0) {
            float2 pp = ((const float2*)p3)[b * NP + i];
            #pragma unroll
            for (int c = 0; c < 8; c++) vr[c] += bc[c] + w0c[c] * pp.x + w1c[c] * pp.y;
            float* o = g_xcat + ((size_t)(b * NP + i)) * (2 * CH) + j;
            *(float4*)o = make_float4(vr[0], vr[1], vr[2], vr[3]);
            *(float4*)(o + 4) = make_float4(vr[4], vr[5], vr[6], vr[7]);
        } else if constexpr (MODE == 1) {
            float bia = p0[i] + p1[i];
            float w0 = p2[2 * i], w1 = p2[2 * i + 1];
            #pragma unroll
            for (int c = 0; c < 8; c++) vr[c] = (vr[c] + bia + w0 * ppx[c] + w1 * ppy[c]) * bvc[c];
            float* o = g_imf + (size_t)b * CH * NP + (size_t)i * NP + j;
            *(float4*)o = make_float4(vr[0], vr[1], vr[2], vr[3]);
            *(float4*)(o + 4) = make_float4(vr[4], vr[5], vr[6], vr[7]);
        } else if constexpr (MODE == 2) {
            float w = g_wv[b * NP + i];
            #pragma unroll
            for (int c = 0; c < 8; c++) vr[c] *= w;
            float* o = g_xcat + ((size_t)(b * NP + i)) * (2 * CH) + CH + j;
            *(float4*)o = make_float4(vr[0], vr[1], vr[2], vr[3]);
            *(float4*)(o + 4) = make_float4(vr[4], vr[5], vr[6], vr[7]);
        } else if constexpr (MODE == 3) {
            #pragma unroll
            for (int c = 0; c < 8; c++) vr[c] += bc[c];
            float* o = g_x + ((size_t)(b * NP + i)) * CH + j;
            *(float4*)o = make_float4(vr[0], vr[1], vr[2], vr[3]);
            *(float4*)(o + 4) = make_float4(vr[4], vr[5], vr[6], vr[7]);
        } else if constexpr (MODE == 4) {
            #pragma unroll
            for (int c = 0; c < 8; c++) vr[c] = fmaxf(vr[c] + bc[c], 0.f);
            float* o = g_h + ((size_t)(b * NP + i)) * FFNC + j;
            *(float4*)o = make_float4(vr[0], vr[1], vr[2], vr[3]);
            *(float4*)(o + 4) = make_float4(vr[4], vr[5], vr[6], vr[7]);
        } else {
            const float* rsd = g_x + ((size_t)(b * NP + i)) * CH + j;
            float4 r0 = *(const float4*)rsd, r1 = *(const float4*)(rsd + 4);
            vr[0] += bc[0] + r0.x; vr[1] += bc[1] + r0.y; vr[2] += bc[2] + r0.z; vr[3] += bc[3] + r0.w;
            vr[4] += bc[4] + r1.x; vr[5] += bc[5] + r1.y; vr[6] += bc[6] + r1.z; vr[7] += bc[7] + r1.w;
            float* o = g_y2 + ((size_t)(b * NP + i)) * CH + j;
            *(float4*)o = make_float4(vr[0], vr[1], vr[2], vr[3]);
            *(float4*)(o + 4) = make_float4(vr[4], vr[5], vr[6], vr[7]);
        }
    }
}

template<int MODE>
__global__ void __launch_bounds__(128) k_gemm(const float* __restrict__ e0,
                                              const float* __restrict__ p0,
                                              const float* __restrict__ p1,
                                              const float* __restrict__ p2,
                                              const float* __restrict__ p3) {
    gemm_body<MODE>(blockIdx.x, blockIdx.y, blockIdx.z, e0, p0, p1, p2, p3);
}

// fused gemm0+gemm1: 256 blocks, first 128 = mode0 (2x32x2), rest = mode1 (16x4x2)
__global__ void __launch_bounds__(128) k_gemm01(
    const float* __restrict__ Wp, const float* __restrict__ bp,
    const float* __restrict__ bqp, const float* __restrict__ Wqp,
    const float* __restrict__ ppos,
    const float* __restrict__ Wi, const float* __restrict__ bi,
    const float* __restrict__ bkp, const float* __restrict__ Wkp,
    const float* __restrict__ ipos) {
    int id = blockIdx.x;
    if (id < 128) {
        int bz = id >> 6, r = id & 63;
        gemm_body<0>(r & 1, r >> 1, bz, Wp, bp, bqp, Wqp, ppos);
    } else {
        id -= 128;
        int bz = id >> 6, r = id & 63;
        gemm_body<1>(r & 15, r >> 4, bz, Wi, bi, bkp, Wkp, ipos);
    }
}

// ---------------- LayerNorm in place on g_x ----------------
__global__ void k_ln(const float* __restrict__ gamma, const float* __restrict__ beta) {
    int row = blockIdx.x * 8 + (threadIdx.x >> 5);
    int lane = threadIdx.x & 31;
    float* x = g_x + (size_t)row * CH + lane * 8;
    float4 v0 = *(float4*)x;
    float4 v1 = *(float4*)(x + 4);
    float s = v0.x + v0.y + v0.z + v0.w + v1.x + v1.y + v1.z + v1.w;
    float s2 = v0.x * v0.x + v0.y * v0.y + v0.z * v0.z + v0.w * v0.w +
               v1.x * v1.x + v1.y * v1.y + v1.z * v1.z + v1.w * v1.w;
    #pragma unroll
    for (int o = 16; o; o >>= 1) {
        s  += __shfl_xor_sync(0xffffffffu, s, o);
        s2 += __shfl_xor_sync(0xffffffffu, s2, o);
    }
    float mu = s * (1.f / CH);
    float var = s2 * (1.f / CH) - mu * mu;
    float inv = rsqrtf(var + 1e-5f);
    int c = lane * 8;
    float4 g0 = *(const float4*)(gamma + c), g1 = *(const float4*)(gamma + c + 4);
    float4 b0 = *(const float4*)(beta + c),  b1 = *(const float4*)(beta + c + 4);
    v0.x = (v0.x - mu) * inv * g0.x + b0.x; v0.y = (v0.y - mu) * inv * g0.y + b0.y;
    v0.z = (v0.z - mu) * inv * g0.z + b0.z; v0.w = (v0.w - mu) * inv * g0.w + b0.w;
    v1.x = (v1.x - mu) * inv * g1.x + b1.x; v1.y = (v1.y - mu) * inv * g1.y + b1.y;
    v1.z = (v1.z - mu) * inv * g1.z + b1.z; v1.w = (v1.w - mu) * inv * g1.w + b1.w;
    *(float4*)x = v0;
    *(float4*)(x + 4) = v1;
}

// ---------------- final LN + prediction head + coalesced outputs ----------------
__global__ void k_final(const float* __restrict__ gamma, const float* __restrict__ beta,
                        const float* __restrict__ Wpred, const float* __restrict__ bpred,
                        const float* __restrict__ ppos,
                        float* __restrict__ out_x, float* __restrict__ out_np,
                        float* __restrict__ out_c) {
    __shared__ float tile[8][260];
    int tid = threadIdx.x;
    int row = blockIdx.x * 8 + (tid >> 5);
    int lane = tid & 31;
    int wid = tid >> 5;
    int b = row >> 11, n = row & (NP - 1);
    const float* y = g_y2 + (size_t)row * CH + lane * 8;
    float4 v0 = *(const float4*)y;
    float4 v1 = *(const float4*)(y + 4);
    float s = v0.x + v0.y + v0.z + v0.w + v1.x + v1.y + v1.z + v1.w;
    float s2 = v0.x * v0.x + v0.y * v0.y + v0.z * v0.z + v0.w * v0.w +
               v1.x * v1.x + v1.y * v1.y + v1.z * v1.z + v1.w * v1.w;
    #pragma unroll
    for (int o = 16; o; o >>= 1) {
        s  += __shfl_xor_sync(0xffffffffu, s, o);
        s2 += __shfl_xor_sync(0xffffffffu, s2, o);
    }
    float mu = s * (1.f / CH);
    float var = s2 * (1.f / CH) - mu * mu;
    float inv = rsqrtf(var + 1e-5f);
    int c = lane * 8;
    float4 g0 = *(const float4*)(gamma + c), g1 = *(const float4*)(gamma + c + 4);
    float4 b0 = *(const float4*)(beta + c),  b1 = *(const float4*)(beta + c + 4);
    v0.x = (v0.x - mu) * inv * g0.x + b0.x; v0.y = (v0.y - mu) * inv * g0.y + b0.y;
    v0.z = (v0.z - mu) * inv * g0.z + b0.z; v0.w = (v0.w - mu) * inv * g0.w + b0.w;
    v1.x = (v1.x - mu) * inv * g1.x + b1.x; v1.y = (v1.y - mu) * inv * g1.y + b1.y;
    v1.z = (v1.z - mu) * inv * g1.z + b1.z; v1.w = (v1.w - mu) * inv * g1.w + b1.w;

    float4 w00 = *(const float4*)(Wpred + c),      w01 = *(const float4*)(Wpred + c + 4);
    float4 w10 = *(const float4*)(Wpred + CH + c), w11 = *(const float4*)(Wpred + CH + c + 4);
    float d0 = v0.x * w00.x + v0.y * w00.y + v0.z * w00.z + v0.w * w00.w +
               v1.x * w01.x + v1.y * w01.y + v1.z * w01.z + v1.w * w01.w;
    float d1 = v0.x * w10.x + v0.y * w10.y + v0.z * w10.z + v0.w * w10.w +
               v1.x * w11.x + v1.y * w11.y + v1.z * w11.z + v1.w * w11.w;
    #pragma unroll
    for (int o = 16; o; o >>= 1) {
        d0 += __shfl_xor_sync(0xffffffffu, d0, o);
        d1 += __shfl_xor_sync(0xffffffffu, d1, o);
    }

    *(float4*)&tile[wid][c] = v0;
    *(float4*)&tile[wid][c + 4] = v1;

    if (lane == 0) {
        float2 pp = ((const float2*)ppos)[b * NP + n];
        float c0 = d0 + bpred[0] + pp.x;
        float c1 = d1 + bpred[1] + pp.y;
        out_c[(size_t)b * 2 * NP + n] = c0;
        out_c[(size_t)b * 2 * NP + NP + n] = c1;
        ((float2*)out_np)[b * NP + n] = make_float2(c0, c1);
    }
    __syncthreads();

    int col = tid;
    int n0 = (blockIdx.x * 8) & (NP - 1);
    int bb = (blockIdx.x * 8) >> 11;
    float* ox = out_x + (size_t)bb * CH * NP + (size_t)col * NP + n0;
    float4 o0 = make_float4(tile[0][col], tile[1][col], tile[2][col], tile[3][col]);
    float4 o1 = make_float4(tile[4][col], tile[5][col], tile[6][col], tile[7][col]);
    *(float4*)ox = o0;
    *(float4*)(ox + 4) = o1;
}

// ---------------- launch ----------------
extern "C" void kernel_launch(void* const* d_in, const int* in_sizes, int n_in,
                              void* d_out, int out_size) {
    const float* ptsf   = (const float*)d_in[0];
    const float* ppos   = (const float*)d_in[1];
    const float* imgf   = (const float*)d_in[2];
    const float* ipos   = (const float*)d_in[3];
    const float* ptscls = (const float*)d_in[4];
    const float* imgcls = (const float*)d_in[5];
    const float* Wp  = (const float*)d_in[6];  const float* bp  = (const float*)d_in[7];
    const float* Wi  = (const float*)d_in[8];  const float* bi  = (const float*)d_in[9];
    const float* Wqp = (const float*)d_in[10]; const float* bqp = (const float*)d_in[11];
    const float* Wkp = (const float*)d_in[12]; const float* bkp = (const float*)d_in[13];
    const float* Wout = (const float*)d_in[14]; const float* bout = (const float*)d_in[15];
    const float* gout = (const float*)d_in[16]; const float* betaout = (const float*)d_in[17];
    const float* Wf1 = (const float*)d_in[18]; const float* bf1 = (const float*)d_in[19];
    const float* Wf2 = (const float*)d_in[20]; const float* bf2 = (const float*)d_in[21];
    const float* gln = (const float*)d_in[22]; const float* bln = (const float*)d_in[23];
    const float* Wpred = (const float*)d_in[24]; const float* bpred = (const float*)d_in[25];

    float* out    = (float*)d_out;
    float* out_x  = out;                                   // [2,256,2048]
    float* out_np = out + (size_t)BSZ * CH * NP;           // [2,2048,2]
    float* out_c  = out_np + (size_t)BSZ * NP * 2;         // [2,2,2048]

    const int IPOT_SMEM = NP * (int)sizeof(float) + 8 * NP * (int)sizeof(__half);  // 40 KB
    cudaFuncSetAttribute(k_ipot_persist, cudaFuncAttributeMaxDynamicSharedMemorySize, IPOT_SMEM);
    const int GEMM_SMEM = (32 * (64 + 4) + 32 * (128 + 4)) * (int)sizeof(float);   // 25600 B

    dim3 tb(32, 8);
    k_cls<<<NROW / 256, 256>>>(ptscls, imgcls);                        // launch 1
    k_transpose2<<<dim3(NP / 32, CH / 32, 2 * BSZ), tb>>>(ptsf, imgf); // launch 2

    // launch 3: ALL 100 IPOT iterations
    k_ipot_persist<<<NBLK, 256, IPOT_SMEM>>>(ppos, ipos);

    // fused projections + positional embeddings (mode0 + mode1 concurrently)
    k_gemm01<<<256, 128, GEMM_SMEM>>>(Wp, bp, bqp, Wqp, ppos, Wi, bi, bkp, Wkp, ipos);

    // attention GEMM: img_att = w ⊙ (Q_fp16 @ imf_scaled^T)
    k_gemm<2><<<dim3(CH / 128, NP / 64, BSZ), 128, GEMM_SMEM>>>(nullptr, nullptr, nullptr, nullptr, nullptr);
    // out projection + LN
    k_gemm<3><<<dim3(CH / 128, NP / 64, BSZ), 128, GEMM_SMEM>>>(Wout, bout, nullptr, nullptr, nullptr);
    k_ln<<<NROW / 8, 256>>>(gout, betaout);
    // FFN
    k_gemm<4><<<dim3(FFNC / 128, NP / 64, BSZ), 128, GEMM_SMEM>>>(Wf1, bf1, nullptr, nullptr, nullptr);
    k_gemm<5><<<dim3(CH / 128, NP / 64, BSZ), 128, GEMM_SMEM>>>(Wf2, bf2, nullptr, nullptr, nullptr);
    // final LN + head + outputs
    k_final<<<NROW / 8, 256>>>(gln, bln, Wpred, bpred, ppos, out_x, out_np, out_c);
}